// round 1
// baseline (speedup 1.0000x reference)
#include <cuda_runtime.h>
#include <cstdint>

// Problem constants
#define BB 2
#define TT 4
#define CC 256
#define HH 128
#define WW 128
#define BT (BB*TT)              // 8
#define NSEQ (BT*WW)            // 1024
#define LL HH                   // 128
#define HEADS 8
#define DH 32
#define MROWS (NSEQ*LL)         // 131072
#define SCALE 0.17677669529663687f

// ---------------- scratch (device globals; no cudaMalloc allowed) ----------
__device__ float g_seq [ (size_t)MROWS * CC ];        // [131072, 256]
__device__ float g_qkv [ (size_t)MROWS * 3 * CC ];    // [131072, 768]
__device__ float g_att [ (size_t)MROWS * CC ];        // [131072, 256]
__device__ float g_proj[ (size_t)MROWS * CC ];        // [131072, 256]

// ---------------------------------------------------------------------------
// Kernel 1: gather/transpose  x(B,T,C,H,W) -> seq[(bt*W+w), h, c]
// grid (W/32, C/32, BT*H), block (32,8). Coalesced read along w, write along c.
// ---------------------------------------------------------------------------
__global__ void gather_seq_kernel(const float* __restrict__ x) {
    __shared__ float tile[32][33];
    const int bt = blockIdx.z >> 7;
    const int h  = blockIdx.z & 127;
    const int wbase = blockIdx.x * 32;
    const int cbase = blockIdx.y * 32;
    const int tx = threadIdx.x, ty = threadIdx.y;

    const float* xb = x + (size_t)bt * CC * HH * WW + (size_t)h * WW;
#pragma unroll
    for (int i = 0; i < 4; i++) {
        int c = cbase + ty + i * 8;
        tile[ty + i * 8][tx] = xb[(size_t)c * (HH * WW) + wbase + tx];
    }
    __syncthreads();
#pragma unroll
    for (int i = 0; i < 4; i++) {
        int w = wbase + ty + i * 8;
        g_seq[((size_t)(bt * WW + w) * LL + h) * CC + cbase + tx] = tile[tx][ty + i * 8];
    }
}

// ---------------------------------------------------------------------------
// Kernels 2 & 4: SGEMM  C[M,N] = A[M,256] * B[256,N] + bias
// BM=128, BN=128, BK=16, 256 threads, 8x8 microtile, 2 CTAs/SM.
// ---------------------------------------------------------------------------
__global__ __launch_bounds__(256, 2)
void gemm_bias_kernel(const float* __restrict__ A, const float* __restrict__ Bm,
                      const float* __restrict__ bias, float* __restrict__ Cm,
                      int N) {
    const int K = CC;
    __shared__ float As[16][132];   // [k][m], padded
    __shared__ float Bs[16][128];   // [k][n]

    const int tid   = threadIdx.x;
    const int mBase = blockIdx.y * 128;
    const int nBase = blockIdx.x * 128;
    const int tx = tid & 15, ty = tid >> 4;

    // load mappings
    const int aRow = tid >> 2;            // 0..63
    const int aK4  = (tid & 3) * 4;       // 0,4,8,12
    const int bK   = tid >> 5;            // 0..7
    const int bCol = (tid & 31) * 4;      // 0..124

    float acc[8][8];
#pragma unroll
    for (int i = 0; i < 8; i++)
#pragma unroll
        for (int j = 0; j < 8; j++) acc[i][j] = 0.f;

    for (int k0 = 0; k0 < K; k0 += 16) {
#pragma unroll
        for (int r = 0; r < 2; r++) {
            const float4 v = *(const float4*)&A[(size_t)(mBase + aRow + r * 64) * K + k0 + aK4];
            As[aK4 + 0][aRow + r * 64] = v.x;
            As[aK4 + 1][aRow + r * 64] = v.y;
            As[aK4 + 2][aRow + r * 64] = v.z;
            As[aK4 + 3][aRow + r * 64] = v.w;
        }
#pragma unroll
        for (int r = 0; r < 2; r++) {
            *(float4*)&Bs[bK + r * 8][bCol] =
                *(const float4*)&Bm[(size_t)(k0 + bK + r * 8) * N + nBase + bCol];
        }
        __syncthreads();

#pragma unroll
        for (int kk = 0; kk < 16; kk++) {
            float a[8], b[8];
            *(float4*)&a[0] = *(const float4*)&As[kk][ty * 8];
            *(float4*)&a[4] = *(const float4*)&As[kk][ty * 8 + 4];
            *(float4*)&b[0] = *(const float4*)&Bs[kk][tx * 8];
            *(float4*)&b[4] = *(const float4*)&Bs[kk][tx * 8 + 4];
#pragma unroll
            for (int i = 0; i < 8; i++)
#pragma unroll
                for (int j = 0; j < 8; j++)
                    acc[i][j] = fmaf(a[i], b[j], acc[i][j]);
        }
        __syncthreads();
    }

    float bc[8];
#pragma unroll
    for (int j = 0; j < 8; j++) bc[j] = bias[nBase + tx * 8 + j];

#pragma unroll
    for (int i = 0; i < 8; i++) {
        float* crow = &Cm[(size_t)(mBase + ty * 8 + i) * N + nBase + tx * 8];
#pragma unroll
        for (int j = 0; j < 8; j += 4) {
            float4 v;
            v.x = acc[i][j + 0] + bc[j + 0];
            v.y = acc[i][j + 1] + bc[j + 1];
            v.z = acc[i][j + 2] + bc[j + 2];
            v.w = acc[i][j + 3] + bc[j + 3];
            *(float4*)&crow[j] = v;
        }
    }
}

// ---------------------------------------------------------------------------
// Kernel 3: attention, one CTA per (n, head). 256 threads.
// smem: qT[32][132], kT[32][132] (transposed), vs[128][33], Ss[128][132]
// ---------------------------------------------------------------------------
#define QT_PAD 132
#define VS_PAD 33
#define SS_PAD 132
#define SMEM_ATT_BYTES ((32*QT_PAD + 32*QT_PAD + 128*VS_PAD + 128*SS_PAD) * 4)

__global__ __launch_bounds__(256)
void attention_kernel(const float* __restrict__ rel_bias) {
    extern __shared__ float sm[];
    float* qT = sm;                       // [32][132]   qT[d][l]
    float* kT = qT + 32 * QT_PAD;         // [32][132]   kT[d][m]
    float* vs = kT + 32 * QT_PAD;         // [128][33]   vs[m][d]
    float* Ss = vs + 128 * VS_PAD;        // [128][132]

    const int n = blockIdx.x >> 3;
    const int h = blockIdx.x & 7;
    const int tid = threadIdx.x;

    // ---- load q,k,v ----
    {
        const float* base = g_qkv + (size_t)n * LL * (3 * CC) + h * DH;
        const int r0 = tid >> 3;           // 0..31
        const int d4 = (tid & 7) * 4;      // 0..28
#pragma unroll
        for (int it = 0; it < 4; it++) {
            const int rr = r0 + it * 32;
            const float* rowp = base + (size_t)rr * (3 * CC);
            float4 q4 = *(const float4*)(rowp + d4);
            float4 k4 = *(const float4*)(rowp + CC + d4);
            float4 v4 = *(const float4*)(rowp + 2 * CC + d4);
            qT[(d4 + 0) * QT_PAD + rr] = q4.x;
            qT[(d4 + 1) * QT_PAD + rr] = q4.y;
            qT[(d4 + 2) * QT_PAD + rr] = q4.z;
            qT[(d4 + 3) * QT_PAD + rr] = q4.w;
            kT[(d4 + 0) * QT_PAD + rr] = k4.x;
            kT[(d4 + 1) * QT_PAD + rr] = k4.y;
            kT[(d4 + 2) * QT_PAD + rr] = k4.z;
            kT[(d4 + 3) * QT_PAD + rr] = k4.w;
            vs[rr * VS_PAD + d4 + 0] = v4.x;
            vs[rr * VS_PAD + d4 + 1] = v4.y;
            vs[rr * VS_PAD + d4 + 2] = v4.z;
            vs[rr * VS_PAD + d4 + 3] = v4.w;
        }
    }
    __syncthreads();

    // ---- S = q @ k^T * scale + rel_bias[h] ----
    {
        const int tx = tid & 15, ty = tid >> 4;
        float accS[8][8];
#pragma unroll
        for (int i = 0; i < 8; i++)
#pragma unroll
            for (int j = 0; j < 8; j++) accS[i][j] = 0.f;

#pragma unroll 4
        for (int dd = 0; dd < 32; dd++) {
            float a[8], b[8];
            *(float4*)&a[0] = *(float4*)&qT[dd * QT_PAD + ty * 8];
            *(float4*)&a[4] = *(float4*)&qT[dd * QT_PAD + ty * 8 + 4];
            *(float4*)&b[0] = *(float4*)&kT[dd * QT_PAD + tx * 8];
            *(float4*)&b[4] = *(float4*)&kT[dd * QT_PAD + tx * 8 + 4];
#pragma unroll
            for (int i = 0; i < 8; i++)
#pragma unroll
                for (int j = 0; j < 8; j++)
                    accS[i][j] = fmaf(a[i], b[j], accS[i][j]);
        }

        const float* rb = rel_bias + (size_t)h * LL * LL;
#pragma unroll
        for (int i = 0; i < 8; i++) {
            const int l = ty * 8 + i;
#pragma unroll
            for (int j = 0; j < 8; j += 4) {
                const int m = tx * 8 + j;
                float4 bz = *(const float4*)&rb[(size_t)l * LL + m];
                float4 v;
                v.x = accS[i][j + 0] * SCALE + bz.x;
                v.y = accS[i][j + 1] * SCALE + bz.y;
                v.z = accS[i][j + 2] * SCALE + bz.z;
                v.w = accS[i][j + 3] * SCALE + bz.w;
                *(float4*)&Ss[l * SS_PAD + m] = v;
            }
        }
    }
    __syncthreads();

    // ---- softmax rows (thread per row, vectorized) ----
    if (tid < 128) {
        float* row = &Ss[tid * SS_PAD];
        float mx = -1e30f;
#pragma unroll 8
        for (int m4 = 0; m4 < 32; m4++) {
            float4 v = *(float4*)&row[m4 * 4];
            mx = fmaxf(mx, fmaxf(fmaxf(v.x, v.y), fmaxf(v.z, v.w)));
        }
        float s = 0.f;
#pragma unroll 8
        for (int m4 = 0; m4 < 32; m4++) {
            float4 v = *(float4*)&row[m4 * 4];
            v.x = __expf(v.x - mx); v.y = __expf(v.y - mx);
            v.z = __expf(v.z - mx); v.w = __expf(v.w - mx);
            s += v.x + v.y + v.z + v.w;
            *(float4*)&row[m4 * 4] = v;
        }
        const float inv = 1.f / s;
#pragma unroll 8
        for (int m4 = 0; m4 < 32; m4++) {
            float4 v = *(float4*)&row[m4 * 4];
            v.x *= inv; v.y *= inv; v.z *= inv; v.w *= inv;
            *(float4*)&row[m4 * 4] = v;
        }
    }
    __syncthreads();

    // ---- O = P @ V ; warp = 32 d-lanes, 16 l-rows per warp ----
    {
        const int d  = tid & 31;
        const int wp = tid >> 5;           // 0..7
        const int l0 = wp * 16;
        float acc[16];
#pragma unroll
        for (int i = 0; i < 16; i++) acc[i] = 0.f;

        for (int m = 0; m < 128; m++) {
            const float vv = vs[m * VS_PAD + d];
#pragma unroll
            for (int i = 0; i < 16; i++)
                acc[i] = fmaf(Ss[(l0 + i) * SS_PAD + m], vv, acc[i]);
        }
#pragma unroll
        for (int i = 0; i < 16; i++) {
            const int l = l0 + i;
            g_att[((size_t)n * LL + l) * CC + h * DH + d] = acc[i];
        }
    }
}

// ---------------------------------------------------------------------------
// Kernel 5: scatter/transpose  proj[(bt*W+w), h, c] -> out(B,T,C,H,W)
// ---------------------------------------------------------------------------
__global__ void scatter_out_kernel(float* __restrict__ out) {
    __shared__ float tile[32][33];
    const int bt = blockIdx.z >> 7;
    const int h  = blockIdx.z & 127;
    const int wbase = blockIdx.x * 32;
    const int cbase = blockIdx.y * 32;
    const int tx = threadIdx.x, ty = threadIdx.y;

#pragma unroll
    for (int i = 0; i < 4; i++) {
        int w = wbase + ty + i * 8;
        tile[ty + i * 8][tx] = g_proj[((size_t)(bt * WW + w) * LL + h) * CC + cbase + tx];
    }
    __syncthreads();
    float* ob = out + (size_t)bt * CC * HH * WW + (size_t)h * WW;
#pragma unroll
    for (int i = 0; i < 4; i++) {
        int c = cbase + ty + i * 8;
        ob[(size_t)c * (HH * WW) + wbase + tx] = tile[tx][ty + i * 8];
    }
}

// ---------------------------------------------------------------------------
extern "C" void kernel_launch(void* const* d_in, const int* in_sizes, int n_in,
                              void* d_out, int out_size) {
    const float* x        = (const float*)d_in[0];
    const float* rel_bias = (const float*)d_in[1];
    const float* Wqkv     = (const float*)d_in[2];
    const float* bqkv     = (const float*)d_in[3];
    const float* Wout     = (const float*)d_in[4];
    const float* bout     = (const float*)d_in[5];
    float* out = (float*)d_out;

    void *p_seq, *p_qkv, *p_att, *p_proj;
    cudaGetSymbolAddress(&p_seq,  g_seq);
    cudaGetSymbolAddress(&p_qkv,  g_qkv);
    cudaGetSymbolAddress(&p_att,  g_att);
    cudaGetSymbolAddress(&p_proj, g_proj);

    cudaFuncSetAttribute(attention_kernel,
                         cudaFuncAttributeMaxDynamicSharedMemorySize,
                         SMEM_ATT_BYTES);

    // 1) gather x -> seq
    gather_seq_kernel<<<dim3(WW / 32, CC / 32, BT * HH), dim3(32, 8)>>>(x);

    // 2) qkv = seq @ Wqkv + bqkv   [131072 x 768]
    gemm_bias_kernel<<<dim3(3 * CC / 128, MROWS / 128), 256>>>(
        (const float*)p_seq, Wqkv, bqkv, (float*)p_qkv, 3 * CC);

    // 3) attention per (n, head)
    attention_kernel<<<NSEQ * HEADS, 256, SMEM_ATT_BYTES>>>(rel_bias);

    // 4) proj = att @ Wout + bout  [131072 x 256]
    gemm_bias_kernel<<<dim3(CC / 128, MROWS / 128), 256>>>(
        (const float*)p_att, Wout, bout, (float*)p_proj, CC);

    // 5) scatter proj -> out
    scatter_out_kernel<<<dim3(WW / 32, CC / 32, BT * HH), dim3(32, 8)>>>(out);
}

// round 2
// speedup vs baseline: 1.0196x; 1.0196x over previous
#include <cuda_runtime.h>
#include <cstdint>

// Problem constants
#define BB 2
#define TT 4
#define CC 256
#define HH 128
#define WW 128
#define BT (BB*TT)              // 8
#define NSEQ (BT*WW)            // 1024
#define LL HH                   // 128
#define HEADS 8
#define DH 32
#define MROWS (NSEQ*LL)         // 131072
#define SCALE 0.17677669529663687f

// ---------------- scratch (device globals; no cudaMalloc allowed) ----------
__device__ float g_seq [ (size_t)MROWS * CC ];        // [131072, 256]
__device__ float g_qkv [ (size_t)MROWS * 3 * CC ];    // [131072, 768]
__device__ float g_att [ (size_t)MROWS * CC ];        // [131072, 256]
__device__ float g_proj[ (size_t)MROWS * CC ];        // [131072, 256]

// ---------------------------------------------------------------------------
// Kernel 1: gather/transpose  x(B,T,C,H,W) -> seq[(bt*W+w), h, c]
// ---------------------------------------------------------------------------
__global__ void gather_seq_kernel(const float* __restrict__ x) {
    __shared__ float tile[32][33];
    const int bt = blockIdx.z >> 7;
    const int h  = blockIdx.z & 127;
    const int wbase = blockIdx.x * 32;
    const int cbase = blockIdx.y * 32;
    const int tx = threadIdx.x, ty = threadIdx.y;

    const float* xb = x + (size_t)bt * CC * HH * WW + (size_t)h * WW;
#pragma unroll
    for (int i = 0; i < 4; i++) {
        int c = cbase + ty + i * 8;
        tile[ty + i * 8][tx] = xb[(size_t)c * (HH * WW) + wbase + tx];
    }
    __syncthreads();
#pragma unroll
    for (int i = 0; i < 4; i++) {
        int w = wbase + ty + i * 8;
        g_seq[((size_t)(bt * WW + w) * LL + h) * CC + cbase + tx] = tile[tx][ty + i * 8];
    }
}

// ---------------------------------------------------------------------------
// Kernels 2 & 4: SGEMM  C[M,N] = A[M,256] * B[256,N] + bias  (unchanged)
// ---------------------------------------------------------------------------
__global__ __launch_bounds__(256, 2)
void gemm_bias_kernel(const float* __restrict__ A, const float* __restrict__ Bm,
                      const float* __restrict__ bias, float* __restrict__ Cm,
                      int N) {
    const int K = CC;
    __shared__ float As[16][132];
    __shared__ float Bs[16][128];

    const int tid   = threadIdx.x;
    const int mBase = blockIdx.y * 128;
    const int nBase = blockIdx.x * 128;
    const int tx = tid & 15, ty = tid >> 4;

    const int aRow = tid >> 2;
    const int aK4  = (tid & 3) * 4;
    const int bK   = tid >> 5;
    const int bCol = (tid & 31) * 4;

    float acc[8][8];
#pragma unroll
    for (int i = 0; i < 8; i++)
#pragma unroll
        for (int j = 0; j < 8; j++) acc[i][j] = 0.f;

    for (int k0 = 0; k0 < K; k0 += 16) {
#pragma unroll
        for (int r = 0; r < 2; r++) {
            const float4 v = *(const float4*)&A[(size_t)(mBase + aRow + r * 64) * K + k0 + aK4];
            As[aK4 + 0][aRow + r * 64] = v.x;
            As[aK4 + 1][aRow + r * 64] = v.y;
            As[aK4 + 2][aRow + r * 64] = v.z;
            As[aK4 + 3][aRow + r * 64] = v.w;
        }
#pragma unroll
        for (int r = 0; r < 2; r++) {
            *(float4*)&Bs[bK + r * 8][bCol] =
                *(const float4*)&Bm[(size_t)(k0 + bK + r * 8) * N + nBase + bCol];
        }
        __syncthreads();

#pragma unroll
        for (int kk = 0; kk < 16; kk++) {
            float a[8], b[8];
            *(float4*)&a[0] = *(const float4*)&As[kk][ty * 8];
            *(float4*)&a[4] = *(const float4*)&As[kk][ty * 8 + 4];
            *(float4*)&b[0] = *(const float4*)&Bs[kk][tx * 8];
            *(float4*)&b[4] = *(const float4*)&Bs[kk][tx * 8 + 4];
#pragma unroll
            for (int i = 0; i < 8; i++)
#pragma unroll
                for (int j = 0; j < 8; j++)
                    acc[i][j] = fmaf(a[i], b[j], acc[i][j]);
        }
        __syncthreads();
    }

    float bc[8];
#pragma unroll
    for (int j = 0; j < 8; j++) bc[j] = bias[nBase + tx * 8 + j];

#pragma unroll
    for (int i = 0; i < 8; i++) {
        float* crow = &Cm[(size_t)(mBase + ty * 8 + i) * N + nBase + tx * 8];
#pragma unroll
        for (int j = 0; j < 8; j += 4) {
            float4 v;
            v.x = acc[i][j + 0] + bc[j + 0];
            v.y = acc[i][j + 1] + bc[j + 1];
            v.z = acc[i][j + 2] + bc[j + 2];
            v.w = acc[i][j + 3] + bc[j + 3];
            *(float4*)&crow[j] = v;
        }
    }
}

// ---------------------------------------------------------------------------
// Kernel 3: attention, one CTA per (n, head). 256 threads, 2 CTAs/SM.
// S stored TRANSPOSED: Ss[m][l]  (so PV reads both operands as float4 rows).
// smem (floats):
//   Ss  [128][132]  at 0        (67584 B)  -- aliases qT/kT (disjoint lifetime)
//     qT [32][132]  at 0        (q * SCALE, layout qT[d][l])
//     kT [32][132]  at 4224     (layout kT[d][m])
//   vs  [128][36]   at 16896    (v, layout vs[m][d])
//   inv [128]       at 21504    (1/rowsum per l)
// total 21632 floats = 86528 B
// ---------------------------------------------------------------------------
#define SS_STRIDE 132
#define VS_STRIDE 36
#define SMEM_ATT_FLOATS (128*SS_STRIDE + 128*VS_STRIDE + 128)
#define SMEM_ATT_BYTES  (SMEM_ATT_FLOATS * 4)

__global__ __launch_bounds__(256, 2)
void attention_kernel(const float* __restrict__ rel_bias) {
    extern __shared__ float sm[];
    float* Ss  = sm;                          // [128][132]
    float* qT  = sm;                          // [32][132] (aliased)
    float* kT  = sm + 32 * SS_STRIDE;         // [32][132] (aliased)
    float* vs  = sm + 128 * SS_STRIDE;        // [128][36]
    float* inv = vs + 128 * VS_STRIDE;        // [128]

    const int n = blockIdx.x >> 3;
    const int h = blockIdx.x & 7;
    const int tid = threadIdx.x;

    // ---- load q (pre-scaled), k, v ----
    {
        const float* base = g_qkv + (size_t)n * LL * (3 * CC) + h * DH;
        const int r0 = tid >> 3;           // 0..31
        const int d4 = (tid & 7) * 4;      // 0..28
#pragma unroll
        for (int it = 0; it < 4; it++) {
            const int rr = r0 + it * 32;
            const float* rowp = base + (size_t)rr * (3 * CC);
            float4 q4 = *(const float4*)(rowp + d4);
            float4 k4 = *(const float4*)(rowp + CC + d4);
            float4 v4 = *(const float4*)(rowp + 2 * CC + d4);
            qT[(d4 + 0) * SS_STRIDE + rr] = q4.x * SCALE;
            qT[(d4 + 1) * SS_STRIDE + rr] = q4.y * SCALE;
            qT[(d4 + 2) * SS_STRIDE + rr] = q4.z * SCALE;
            qT[(d4 + 3) * SS_STRIDE + rr] = q4.w * SCALE;
            kT[(d4 + 0) * SS_STRIDE + rr] = k4.x;
            kT[(d4 + 1) * SS_STRIDE + rr] = k4.y;
            kT[(d4 + 2) * SS_STRIDE + rr] = k4.z;
            kT[(d4 + 3) * SS_STRIDE + rr] = k4.w;
            vs[rr * VS_STRIDE + d4 + 0] = v4.x;
            vs[rr * VS_STRIDE + d4 + 1] = v4.y;
            vs[rr * VS_STRIDE + d4 + 2] = v4.z;
            vs[rr * VS_STRIDE + d4 + 3] = v4.w;
        }
    }
    __syncthreads();

    // ---- S^T = k @ q^T : accS[i][j], row m = ty*8+i, col l = tx*8+j ----
    {
        const int tx = tid & 15, ty = tid >> 4;
        float accS[8][8];
#pragma unroll
        for (int i = 0; i < 8; i++)
#pragma unroll
            for (int j = 0; j < 8; j++) accS[i][j] = 0.f;

#pragma unroll 4
        for (int dd = 0; dd < 32; dd++) {
            float a[8], b[8];
            *(float4*)&a[0] = *(float4*)&kT[dd * SS_STRIDE + ty * 8];
            *(float4*)&a[4] = *(float4*)&kT[dd * SS_STRIDE + ty * 8 + 4];
            *(float4*)&b[0] = *(float4*)&qT[dd * SS_STRIDE + tx * 8];
            *(float4*)&b[4] = *(float4*)&qT[dd * SS_STRIDE + tx * 8 + 4];
#pragma unroll
            for (int i = 0; i < 8; i++)
#pragma unroll
                for (int j = 0; j < 8; j++)
                    accS[i][j] = fmaf(a[i], b[j], accS[i][j]);
        }

        __syncthreads();   // all reads of qT/kT done before Ss overwrites them

#pragma unroll
        for (int i = 0; i < 8; i++) {
            const int m = ty * 8 + i;
            float* srow = &Ss[m * SS_STRIDE + tx * 8];
            *(float4*)&srow[0] = *(float4*)&accS[i][0];
            *(float4*)&srow[4] = *(float4*)&accS[i][4];
        }
    }
    __syncthreads();

    // ---- softmax over m for each l (thread per l), bias folded in ----
    if (tid < 128) {
        const int l = tid;
        const float* rbl = rel_bias + ((size_t)h * LL + l) * LL;
        float mx = -1e30f;
        // pass 1: add bias, track max, store biased value back
#pragma unroll 8
        for (int m4 = 0; m4 < 32; m4++) {
            float4 b4 = *(const float4*)&rbl[m4 * 4];
            float v0 = Ss[(m4 * 4 + 0) * SS_STRIDE + l] + b4.x;
            float v1 = Ss[(m4 * 4 + 1) * SS_STRIDE + l] + b4.y;
            float v2 = Ss[(m4 * 4 + 2) * SS_STRIDE + l] + b4.z;
            float v3 = Ss[(m4 * 4 + 3) * SS_STRIDE + l] + b4.w;
            Ss[(m4 * 4 + 0) * SS_STRIDE + l] = v0;
            Ss[(m4 * 4 + 1) * SS_STRIDE + l] = v1;
            Ss[(m4 * 4 + 2) * SS_STRIDE + l] = v2;
            Ss[(m4 * 4 + 3) * SS_STRIDE + l] = v3;
            mx = fmaxf(mx, fmaxf(fmaxf(v0, v1), fmaxf(v2, v3)));
        }
        // pass 2: exp + sum (normalization deferred to PV epilogue)
        float s = 0.f;
#pragma unroll 8
        for (int m = 0; m < 128; m++) {
            float e = __expf(Ss[m * SS_STRIDE + l] - mx);
            Ss[m * SS_STRIDE + l] = e;
            s += e;
        }
        inv[l] = 1.f / s;
    }
    __syncthreads();

    // ---- O = P^T(trans-stored) @ V : 4x4 register tile, float4 LDS both ----
    {
        const int lt = tid & 31;           // l-group: rows l = lt*4 .. lt*4+3
        const int dt = tid >> 5;           // d-group: cols d = dt*4 .. dt*4+3
        float acc[4][4];
#pragma unroll
        for (int i = 0; i < 4; i++)
#pragma unroll
            for (int j = 0; j < 4; j++) acc[i][j] = 0.f;

#pragma unroll 4
        for (int m = 0; m < 128; m++) {
            float4 a = *(float4*)&Ss[m * SS_STRIDE + lt * 4];   // conflict-free
            float4 b = *(float4*)&vs[m * VS_STRIDE + dt * 4];   // broadcast
            acc[0][0] = fmaf(a.x, b.x, acc[0][0]);
            acc[0][1] = fmaf(a.x, b.y, acc[0][1]);
            acc[0][2] = fmaf(a.x, b.z, acc[0][2]);
            acc[0][3] = fmaf(a.x, b.w, acc[0][3]);
            acc[1][0] = fmaf(a.y, b.x, acc[1][0]);
            acc[1][1] = fmaf(a.y, b.y, acc[1][1]);
            acc[1][2] = fmaf(a.y, b.z, acc[1][2]);
            acc[1][3] = fmaf(a.y, b.w, acc[1][3]);
            acc[2][0] = fmaf(a.z, b.x, acc[2][0]);
            acc[2][1] = fmaf(a.z, b.y, acc[2][1]);
            acc[2][2] = fmaf(a.z, b.z, acc[2][2]);
            acc[2][3] = fmaf(a.z, b.w, acc[2][3]);
            acc[3][0] = fmaf(a.w, b.x, acc[3][0]);
            acc[3][1] = fmaf(a.w, b.y, acc[3][1]);
            acc[3][2] = fmaf(a.w, b.z, acc[3][2]);
            acc[3][3] = fmaf(a.w, b.w, acc[3][3]);
        }

#pragma unroll
        for (int i = 0; i < 4; i++) {
            const int l = lt * 4 + i;
            const float s = inv[l];
            float4 v;
            v.x = acc[i][0] * s; v.y = acc[i][1] * s;
            v.z = acc[i][2] * s; v.w = acc[i][3] * s;
            *(float4*)&g_att[((size_t)n * LL + l) * CC + h * DH + dt * 4] = v;
        }
    }
}

// ---------------------------------------------------------------------------
// Kernel 5: scatter/transpose  proj[(bt*W+w), h, c] -> out(B,T,C,H,W)
// ---------------------------------------------------------------------------
__global__ void scatter_out_kernel(float* __restrict__ out) {
    __shared__ float tile[32][33];
    const int bt = blockIdx.z >> 7;
    const int h  = blockIdx.z & 127;
    const int wbase = blockIdx.x * 32;
    const int cbase = blockIdx.y * 32;
    const int tx = threadIdx.x, ty = threadIdx.y;

#pragma unroll
    for (int i = 0; i < 4; i++) {
        int w = wbase + ty + i * 8;
        tile[ty + i * 8][tx] = g_proj[((size_t)(bt * WW + w) * LL + h) * CC + cbase + tx];
    }
    __syncthreads();
    float* ob = out + (size_t)bt * CC * HH * WW + (size_t)h * WW;
#pragma unroll
    for (int i = 0; i < 4; i++) {
        int c = cbase + ty + i * 8;
        ob[(size_t)c * (HH * WW) + wbase + tx] = tile[tx][ty + i * 8];
    }
}

// ---------------------------------------------------------------------------
extern "C" void kernel_launch(void* const* d_in, const int* in_sizes, int n_in,
                              void* d_out, int out_size) {
    const float* x        = (const float*)d_in[0];
    const float* rel_bias = (const float*)d_in[1];
    const float* Wqkv     = (const float*)d_in[2];
    const float* bqkv     = (const float*)d_in[3];
    const float* Wout     = (const float*)d_in[4];
    const float* bout     = (const float*)d_in[5];
    float* out = (float*)d_out;

    void *p_seq, *p_qkv, *p_att, *p_proj;
    cudaGetSymbolAddress(&p_seq,  g_seq);
    cudaGetSymbolAddress(&p_qkv,  g_qkv);
    cudaGetSymbolAddress(&p_att,  g_att);
    cudaGetSymbolAddress(&p_proj, g_proj);

    cudaFuncSetAttribute(attention_kernel,
                         cudaFuncAttributeMaxDynamicSharedMemorySize,
                         SMEM_ATT_BYTES);

    // 1) gather x -> seq
    gather_seq_kernel<<<dim3(WW / 32, CC / 32, BT * HH), dim3(32, 8)>>>(x);

    // 2) qkv = seq @ Wqkv + bqkv   [131072 x 768]
    gemm_bias_kernel<<<dim3(3 * CC / 128, MROWS / 128), 256>>>(
        (const float*)p_seq, Wqkv, bqkv, (float*)p_qkv, 3 * CC);

    // 3) attention per (n, head)
    attention_kernel<<<NSEQ * HEADS, 256, SMEM_ATT_BYTES>>>(rel_bias);

    // 4) proj = att @ Wout + bout  [131072 x 256]
    gemm_bias_kernel<<<dim3(CC / 128, MROWS / 128), 256>>>(
        (const float*)p_att, Wout, bout, (float*)p_proj, CC);

    // 5) scatter proj -> out
    scatter_out_kernel<<<dim3(WW / 32, CC / 32, BT * HH), dim3(32, 8)>>>(out);
}

// round 4
// speedup vs baseline: 1.3321x; 1.3065x over previous
#include <cuda_runtime.h>
#include <cuda_bf16.h>
#include <cstdint>

// Problem constants
#define BB 2
#define TT 4
#define CC 256
#define HH 128
#define WW 128
#define BT (BB*TT)              // 8
#define NSEQ (BT*WW)            // 1024
#define LL HH                   // 128
#define HEADS 8
#define DH 32
#define MROWS (NSEQ*LL)         // 131072
#define SCALE 0.17677669529663687f

// ---------------- scratch (device globals; no cudaMalloc allowed) ----------
__device__ __nv_bfloat16 g_seq_hi[(size_t)MROWS * CC];
__device__ __nv_bfloat16 g_seq_lo[(size_t)MROWS * CC];
__device__ float         g_qkv   [(size_t)MROWS * 3 * CC];
__device__ __nv_bfloat16 g_att_hi[(size_t)MROWS * CC];
__device__ __nv_bfloat16 g_att_lo[(size_t)MROWS * CC];
__device__ float         g_proj  [(size_t)MROWS * CC];
// transposed + split weights: WT[n][k]
__device__ __nv_bfloat16 g_WqkvT_hi[3 * CC * CC];
__device__ __nv_bfloat16 g_WqkvT_lo[3 * CC * CC];
__device__ __nv_bfloat16 g_WoutT_hi[CC * CC];
__device__ __nv_bfloat16 g_WoutT_lo[CC * CC];

// ======================= baseline-PTX helpers (sm_80+) =====================
__device__ __forceinline__ uint32_t smem_u32(const void* p) {
    uint32_t a;
    asm("{ .reg .u64 t; cvta.to.shared.u64 t, %1; cvt.u32.u64 %0, t; }"
        : "=r"(a) : "l"(p));
    return a;
}
#define LDMX4(r0, r1, r2, r3, addr) \
    asm volatile("ldmatrix.sync.aligned.m8n8.x4.shared.b16 {%0,%1,%2,%3}, [%4];" \
                 : "=r"(r0), "=r"(r1), "=r"(r2), "=r"(r3) : "r"(addr))
#define MMA16816(d, a, b) \
    asm volatile("mma.sync.aligned.m16n8k16.row.col.f32.bf16.bf16.f32 " \
                 "{%0,%1,%2,%3}, {%4,%5,%6,%7}, {%8,%9}, {%0,%1,%2,%3};" \
                 : "+f"((d)[0]), "+f"((d)[1]), "+f"((d)[2]), "+f"((d)[3]) \
                 : "r"((a)[0]), "r"((a)[1]), "r"((a)[2]), "r"((a)[3]), \
                   "r"((b)[0]), "r"((b)[1]))
#define SW128(off) ((off) ^ (((off) >> 3) & 0x70))

// ---------------------------------------------------------------------------
// Kernel 1: gather/transpose  x(B,T,C,H,W) -> seq_hi/lo[(bt*W+w), h, c] (bf16)
// ---------------------------------------------------------------------------
__global__ void gather_seq_kernel(const float* __restrict__ x) {
    __shared__ float tile[32][33];
    const int bt = blockIdx.z >> 7;
    const int h  = blockIdx.z & 127;
    const int wbase = blockIdx.x * 32;
    const int cbase = blockIdx.y * 32;
    const int tx = threadIdx.x, ty = threadIdx.y;

    const float* xb = x + (size_t)bt * CC * HH * WW + (size_t)h * WW;
#pragma unroll
    for (int i = 0; i < 4; i++) {
        int c = cbase + ty + i * 8;
        tile[ty + i * 8][tx] = xb[(size_t)c * (HH * WW) + wbase + tx];
    }
    __syncthreads();
#pragma unroll
    for (int i = 0; i < 4; i++) {
        int w = wbase + ty + i * 8;
        float v = tile[tx][ty + i * 8];
        __nv_bfloat16 hi = __float2bfloat16(v);
        float lo = v - __bfloat162float(hi);
        size_t idx = ((size_t)(bt * WW + w) * LL + h) * CC + cbase + tx;
        g_seq_hi[idx] = hi;
        g_seq_lo[idx] = __float2bfloat16(lo);
    }
}

// ---------------------------------------------------------------------------
// Kernel 1b: weight prep — transpose + bf16 split.  WT[n][k] = W[k][n]
// ---------------------------------------------------------------------------
__global__ void wprep_kernel(const float* __restrict__ Wqkv,
                             const float* __restrict__ Wout) {
    int i = blockIdx.x * 256 + threadIdx.x;
    const int NQ = 3 * CC;
    if (i < NQ * CC) {
        int n = i / CC, k = i % CC;
        float v = Wqkv[(size_t)k * NQ + n];
        __nv_bfloat16 hi = __float2bfloat16(v);
        g_WqkvT_hi[(size_t)n * CC + k] = hi;
        g_WqkvT_lo[(size_t)n * CC + k] = __float2bfloat16(v - __bfloat162float(hi));
    }
    if (i < CC * CC) {
        int n = i / CC, k = i % CC;
        float v = Wout[(size_t)k * CC + n];
        __nv_bfloat16 hi = __float2bfloat16(v);
        g_WoutT_hi[(size_t)n * CC + k] = hi;
        g_WoutT_lo[(size_t)n * CC + k] = __float2bfloat16(v - __bfloat162float(hi));
    }
}

// ---------------------------------------------------------------------------
// Kernels 2 & 4: mma.sync bf16x3 GEMM.  C[M,N] = A[M,256]*WT[N,256]^T + bias
// CTA 128x128, K chunks of 64, smem tiles Ahi/Alo/Bhi/Blo 128x64 bf16 SW128.
// 8 warps = 2(m) x 4(n); warp tile 64x32 via m16n8k16.
// ---------------------------------------------------------------------------
#define GK 256
#define KC 64
#define TILE_BYTES 16384                  // 128 rows * 128 B
#define GEMM_SMEM (4 * TILE_BYTES)

__global__ __launch_bounds__(256)
void gemm_mma_kernel(const __nv_bfloat16* __restrict__ Ahi,
                     const __nv_bfloat16* __restrict__ Alo,
                     const __nv_bfloat16* __restrict__ Bhi,
                     const __nv_bfloat16* __restrict__ Blo,
                     const float* __restrict__ bias,
                     float* __restrict__ Cm, int N) {
    extern __shared__ char smc[];
    char* t_ahi = smc;
    char* t_alo = smc + TILE_BYTES;
    char* t_bhi = smc + 2 * TILE_BYTES;
    char* t_blo = smc + 3 * TILE_BYTES;
    const uint32_t s_ahi = smem_u32(t_ahi);
    const uint32_t s_alo = smem_u32(t_alo);
    const uint32_t s_bhi = smem_u32(t_bhi);
    const uint32_t s_blo = smem_u32(t_blo);

    const int tid = threadIdx.x;
    const int wid = tid >> 5;
    const int lid = tid & 31;
    const int mBase = blockIdx.y * 128;
    const int nBase = blockIdx.x * 128;
    const int wm = (wid & 1) * 64;       // warp m-offset in tile
    const int wn = (wid >> 1) * 32;      // warp n-offset in tile

    // loader mapping
    const int trow  = tid >> 1;          // 0..127
    const int thalf = (tid & 1) * 32;    // element offset in 64-elem chunk

    // ldmatrix lane addressing (byte offsets within a tile, pre-swizzle)
    const int lr = lid & 7;
    const int lt = lid >> 3;             // tile index 0..3
    // A tiles: row = base + lr + (lt&1)*8 ; kc = (lt>>1)*8
    const uint32_t a_off0 = (uint32_t)( (lr + (lt & 1) * 8) * 128 + ((lt >> 1) * 8) * 2 );
    // B tiles: row = base + lr + (lt>>1)*8 ; kc = (lt&1)*8
    const uint32_t b_off0 = (uint32_t)( (lr + (lt >> 1) * 8) * 128 + ((lt & 1) * 8) * 2 );

    float d[4][4][4];
#pragma unroll
    for (int i = 0; i < 4; i++)
#pragma unroll
        for (int j = 0; j < 4; j++)
#pragma unroll
            for (int r = 0; r < 4; r++) d[i][j][r] = 0.f;

    for (int c = 0; c < 4; c++) {
        const int k0 = c * KC;
        // ---- load chunk into smem (64 B per thread per tile) ----
        {
            const size_t arow = (size_t)(mBase + trow) * GK + k0 + thalf;
            const size_t brow = (size_t)(nBase + trow) * GK + k0 + thalf;
            const uint4* pAh = (const uint4*)(Ahi + arow);
            const uint4* pAl = (const uint4*)(Alo + arow);
            const uint4* pBh = (const uint4*)(Bhi + brow);
            const uint4* pBl = (const uint4*)(Blo + brow);
            const uint32_t ob = trow * 128 + thalf * 2;
#pragma unroll
            for (int i = 0; i < 4; i++) {
                const uint32_t sw = SW128(ob + i * 16);
                *(uint4*)(t_ahi + sw) = pAh[i];
                *(uint4*)(t_alo + sw) = pAl[i];
                *(uint4*)(t_bhi + sw) = pBh[i];
                *(uint4*)(t_blo + sw) = pBl[i];
            }
        }
        __syncthreads();

        // ---- consume: 4 k16 steps ----
#pragma unroll
        for (int ks = 0; ks < 4; ks++) {
            const uint32_t kb = ks * 32;   // 16 bf16 = 32 B
            uint32_t ah[4][4], al[4][4], bh[4][2], bl[4][2];
#pragma unroll
            for (int mi = 0; mi < 4; mi++) {
                const uint32_t off = SW128(a_off0 + (wm + mi * 16) * 128 + kb);
                LDMX4(ah[mi][0], ah[mi][1], ah[mi][2], ah[mi][3], s_ahi + off);
                LDMX4(al[mi][0], al[mi][1], al[mi][2], al[mi][3], s_alo + off);
            }
#pragma unroll
            for (int ng = 0; ng < 2; ng++) {   // n16 groups
                const uint32_t off = SW128(b_off0 + (wn + ng * 16) * 128 + kb);
                uint32_t r0, r1, r2, r3;
                LDMX4(r0, r1, r2, r3, s_bhi + off);
                bh[ng * 2][0] = r0; bh[ng * 2][1] = r1;
                bh[ng * 2 + 1][0] = r2; bh[ng * 2 + 1][1] = r3;
                LDMX4(r0, r1, r2, r3, s_blo + off);
                bl[ng * 2][0] = r0; bl[ng * 2][1] = r1;
                bl[ng * 2 + 1][0] = r2; bl[ng * 2 + 1][1] = r3;
            }
#pragma unroll
            for (int mi = 0; mi < 4; mi++)
#pragma unroll
                for (int nj = 0; nj < 4; nj++) {
                    MMA16816(d[mi][nj], ah[mi], bh[nj]);
                    MMA16816(d[mi][nj], ah[mi], bl[nj]);
                    MMA16816(d[mi][nj], al[mi], bh[nj]);
                }
        }
        __syncthreads();
    }

    // ---- epilogue: D frag m16n8, lane: rows l/4 (+8), cols (l&3)*2 (+1) ----
    const int erow = lid >> 2;
    const int ecol = (lid & 3) * 2;
#pragma unroll
    for (int nj = 0; nj < 4; nj++) {
        const int ncol = nBase + wn + nj * 8 + ecol;
        const float bx = bias[ncol], by = bias[ncol + 1];
#pragma unroll
        for (int mi = 0; mi < 4; mi++) {
            const int r0 = mBase + wm + mi * 16 + erow;
            float2 v0 = make_float2(d[mi][nj][0] + bx, d[mi][nj][1] + by);
            float2 v1 = make_float2(d[mi][nj][2] + bx, d[mi][nj][3] + by);
            *(float2*)&Cm[(size_t)r0 * N + ncol]       = v0;
            *(float2*)&Cm[(size_t)(r0 + 8) * N + ncol] = v1;
        }
    }
}

// ---------------------------------------------------------------------------
// Kernel 3: attention (fp32, unchanged; epilogue emits bf16 hi/lo)
// ---------------------------------------------------------------------------
#define SS_STRIDE 132
#define VS_STRIDE 36
#define SMEM_ATT_FLOATS (128*SS_STRIDE + 128*VS_STRIDE + 128)
#define SMEM_ATT_BYTES  (SMEM_ATT_FLOATS * 4)

__global__ __launch_bounds__(256, 2)
void attention_kernel(const float* __restrict__ rel_bias) {
    extern __shared__ float smf[];
    float* Ss  = smf;
    float* qT  = smf;
    float* kT  = smf + 32 * SS_STRIDE;
    float* vs  = smf + 128 * SS_STRIDE;
    float* inv = vs + 128 * VS_STRIDE;

    const int n  = blockIdx.x >> 3;
    const int hd = blockIdx.x & 7;
    const int tid = threadIdx.x;

    {
        const float* base = g_qkv + (size_t)n * LL * (3 * CC) + hd * DH;
        const int r0 = tid >> 3;
        const int d4 = (tid & 7) * 4;
#pragma unroll
        for (int it = 0; it < 4; it++) {
            const int rr = r0 + it * 32;
            const float* rowp = base + (size_t)rr * (3 * CC);
            float4 q4 = *(const float4*)(rowp + d4);
            float4 k4 = *(const float4*)(rowp + CC + d4);
            float4 v4 = *(const float4*)(rowp + 2 * CC + d4);
            qT[(d4 + 0) * SS_STRIDE + rr] = q4.x * SCALE;
            qT[(d4 + 1) * SS_STRIDE + rr] = q4.y * SCALE;
            qT[(d4 + 2) * SS_STRIDE + rr] = q4.z * SCALE;
            qT[(d4 + 3) * SS_STRIDE + rr] = q4.w * SCALE;
            kT[(d4 + 0) * SS_STRIDE + rr] = k4.x;
            kT[(d4 + 1) * SS_STRIDE + rr] = k4.y;
            kT[(d4 + 2) * SS_STRIDE + rr] = k4.z;
            kT[(d4 + 3) * SS_STRIDE + rr] = k4.w;
            vs[rr * VS_STRIDE + d4 + 0] = v4.x;
            vs[rr * VS_STRIDE + d4 + 1] = v4.y;
            vs[rr * VS_STRIDE + d4 + 2] = v4.z;
            vs[rr * VS_STRIDE + d4 + 3] = v4.w;
        }
    }
    __syncthreads();

    {
        const int tx = tid & 15, ty = tid >> 4;
        float accS[8][8];
#pragma unroll
        for (int i = 0; i < 8; i++)
#pragma unroll
            for (int j = 0; j < 8; j++) accS[i][j] = 0.f;

#pragma unroll 4
        for (int dd = 0; dd < 32; dd++) {
            float a[8], b[8];
            *(float4*)&a[0] = *(float4*)&kT[dd * SS_STRIDE + ty * 8];
            *(float4*)&a[4] = *(float4*)&kT[dd * SS_STRIDE + ty * 8 + 4];
            *(float4*)&b[0] = *(float4*)&qT[dd * SS_STRIDE + tx * 8];
            *(float4*)&b[4] = *(float4*)&qT[dd * SS_STRIDE + tx * 8 + 4];
#pragma unroll
            for (int i = 0; i < 8; i++)
#pragma unroll
                for (int j = 0; j < 8; j++)
                    accS[i][j] = fmaf(a[i], b[j], accS[i][j]);
        }
        __syncthreads();
#pragma unroll
        for (int i = 0; i < 8; i++) {
            const int m = ty * 8 + i;
            float* srow = &Ss[m * SS_STRIDE + tx * 8];
            *(float4*)&srow[0] = *(float4*)&accS[i][0];
            *(float4*)&srow[4] = *(float4*)&accS[i][4];
        }
    }
    __syncthreads();

    if (tid < 128) {
        const int l = tid;
        const float* rbl = rel_bias + ((size_t)hd * LL + l) * LL;
        float mx = -1e30f;
#pragma unroll 8
        for (int m4 = 0; m4 < 32; m4++) {
            float4 b4 = *(const float4*)&rbl[m4 * 4];
            float v0 = Ss[(m4 * 4 + 0) * SS_STRIDE + l] + b4.x;
            float v1 = Ss[(m4 * 4 + 1) * SS_STRIDE + l] + b4.y;
            float v2 = Ss[(m4 * 4 + 2) * SS_STRIDE + l] + b4.z;
            float v3 = Ss[(m4 * 4 + 3) * SS_STRIDE + l] + b4.w;
            Ss[(m4 * 4 + 0) * SS_STRIDE + l] = v0;
            Ss[(m4 * 4 + 1) * SS_STRIDE + l] = v1;
            Ss[(m4 * 4 + 2) * SS_STRIDE + l] = v2;
            Ss[(m4 * 4 + 3) * SS_STRIDE + l] = v3;
            mx = fmaxf(mx, fmaxf(fmaxf(v0, v1), fmaxf(v2, v3)));
        }
        float s = 0.f;
#pragma unroll 8
        for (int m = 0; m < 128; m++) {
            float e = __expf(Ss[m * SS_STRIDE + l] - mx);
            Ss[m * SS_STRIDE + l] = e;
            s += e;
        }
        inv[l] = 1.f / s;
    }
    __syncthreads();

    {
        const int lt = tid & 31;
        const int dt = tid >> 5;
        float acc[4][4];
#pragma unroll
        for (int i = 0; i < 4; i++)
#pragma unroll
            for (int j = 0; j < 4; j++) acc[i][j] = 0.f;

#pragma unroll 4
        for (int m = 0; m < 128; m++) {
            float4 a = *(float4*)&Ss[m * SS_STRIDE + lt * 4];
            float4 b = *(float4*)&vs[m * VS_STRIDE + dt * 4];
            acc[0][0] = fmaf(a.x, b.x, acc[0][0]);
            acc[0][1] = fmaf(a.x, b.y, acc[0][1]);
            acc[0][2] = fmaf(a.x, b.z, acc[0][2]);
            acc[0][3] = fmaf(a.x, b.w, acc[0][3]);
            acc[1][0] = fmaf(a.y, b.x, acc[1][0]);
            acc[1][1] = fmaf(a.y, b.y, acc[1][1]);
            acc[1][2] = fmaf(a.y, b.z, acc[1][2]);
            acc[1][3] = fmaf(a.y, b.w, acc[1][3]);
            acc[2][0] = fmaf(a.z, b.x, acc[2][0]);
            acc[2][1] = fmaf(a.z, b.y, acc[2][1]);
            acc[2][2] = fmaf(a.z, b.z, acc[2][2]);
            acc[2][3] = fmaf(a.z, b.w, acc[2][3]);
            acc[3][0] = fmaf(a.w, b.x, acc[3][0]);
            acc[3][1] = fmaf(a.w, b.y, acc[3][1]);
            acc[3][2] = fmaf(a.w, b.z, acc[3][2]);
            acc[3][3] = fmaf(a.w, b.w, acc[3][3]);
        }

#pragma unroll
        for (int i = 0; i < 4; i++) {
            const int l = lt * 4 + i;
            const float s = inv[l];
            __nv_bfloat16 hb[4], lb[4];
#pragma unroll
            for (int j = 0; j < 4; j++) {
                float o = acc[i][j] * s;
                hb[j] = __float2bfloat16(o);
                lb[j] = __float2bfloat16(o - __bfloat162float(hb[j]));
            }
            size_t off = ((size_t)n * LL + l) * CC + hd * DH + dt * 4;
            *(uint2*)&g_att_hi[off] = *(uint2*)hb;
            *(uint2*)&g_att_lo[off] = *(uint2*)lb;
        }
    }
}

// ---------------------------------------------------------------------------
// Kernel 5: scatter/transpose  proj[(bt*W+w), h, c] -> out(B,T,C,H,W)
// ---------------------------------------------------------------------------
__global__ void scatter_out_kernel(float* __restrict__ out) {
    __shared__ float tile[32][33];
    const int bt = blockIdx.z >> 7;
    const int h  = blockIdx.z & 127;
    const int wbase = blockIdx.x * 32;
    const int cbase = blockIdx.y * 32;
    const int tx = threadIdx.x, ty = threadIdx.y;

#pragma unroll
    for (int i = 0; i < 4; i++) {
        int w = wbase + ty + i * 8;
        tile[ty + i * 8][tx] = g_proj[((size_t)(bt * WW + w) * LL + h) * CC + cbase + tx];
    }
    __syncthreads();
    float* ob = out + (size_t)bt * CC * HH * WW + (size_t)h * WW;
#pragma unroll
    for (int i = 0; i < 4; i++) {
        int c = cbase + ty + i * 8;
        ob[(size_t)c * (HH * WW) + wbase + tx] = tile[tx][ty + i * 8];
    }
}

// ---------------------------------------------------------------------------
extern "C" void kernel_launch(void* const* d_in, const int* in_sizes, int n_in,
                              void* d_out, int out_size) {
    const float* x        = (const float*)d_in[0];
    const float* rel_bias = (const float*)d_in[1];
    const float* Wqkv     = (const float*)d_in[2];
    const float* bqkv     = (const float*)d_in[3];
    const float* Wout     = (const float*)d_in[4];
    const float* bout     = (const float*)d_in[5];
    float* out = (float*)d_out;

    void *p_qkv, *p_proj;
    void *p_shi, *p_slo, *p_ahi, *p_alo;
    void *p_wqh, *p_wql, *p_woh, *p_wol;
    cudaGetSymbolAddress(&p_qkv,  g_qkv);
    cudaGetSymbolAddress(&p_proj, g_proj);
    cudaGetSymbolAddress(&p_shi, g_seq_hi);
    cudaGetSymbolAddress(&p_slo, g_seq_lo);
    cudaGetSymbolAddress(&p_ahi, g_att_hi);
    cudaGetSymbolAddress(&p_alo, g_att_lo);
    cudaGetSymbolAddress(&p_wqh, g_WqkvT_hi);
    cudaGetSymbolAddress(&p_wql, g_WqkvT_lo);
    cudaGetSymbolAddress(&p_woh, g_WoutT_hi);
    cudaGetSymbolAddress(&p_wol, g_WoutT_lo);

    cudaFuncSetAttribute(attention_kernel,
                         cudaFuncAttributeMaxDynamicSharedMemorySize,
                         SMEM_ATT_BYTES);
    cudaFuncSetAttribute(gemm_mma_kernel,
                         cudaFuncAttributeMaxDynamicSharedMemorySize,
                         GEMM_SMEM);

    // 1) gather x -> seq hi/lo (bf16 split)
    gather_seq_kernel<<<dim3(WW / 32, CC / 32, BT * HH), dim3(32, 8)>>>(x);

    // 1b) weight transpose + split
    wprep_kernel<<<(3 * CC * CC + 255) / 256, 256>>>(Wqkv, Wout);

    // 2) qkv = seq @ Wqkv + bqkv   (mma.sync bf16x3)
    gemm_mma_kernel<<<dim3(3 * CC / 128, MROWS / 128), 256, GEMM_SMEM>>>(
        (const __nv_bfloat16*)p_shi, (const __nv_bfloat16*)p_slo,
        (const __nv_bfloat16*)p_wqh, (const __nv_bfloat16*)p_wql,
        bqkv, (float*)p_qkv, 3 * CC);

    // 3) attention per (n, head)
    attention_kernel<<<NSEQ * HEADS, 256, SMEM_ATT_BYTES>>>(rel_bias);

    // 4) proj = att @ Wout + bout  (mma.sync bf16x3)
    gemm_mma_kernel<<<dim3(CC / 128, MROWS / 128), 256, GEMM_SMEM>>>(
        (const __nv_bfloat16*)p_ahi, (const __nv_bfloat16*)p_alo,
        (const __nv_bfloat16*)p_woh, (const __nv_bfloat16*)p_wol,
        bout, (float*)p_proj, CC);

    // 5) scatter proj -> out
    scatter_out_kernel<<<dim3(WW / 32, CC / 32, BT * HH), dim3(32, 8)>>>(out);
}

// round 5
// speedup vs baseline: 1.5976x; 1.1993x over previous
#include <cuda_runtime.h>
#include <cuda_bf16.h>
#include <cstdint>

// Problem constants
#define BB 2
#define TT 4
#define CC 256
#define HH 128
#define WW 128
#define BT (BB*TT)              // 8
#define NSEQ (BT*WW)            // 1024
#define LL HH                   // 128
#define HEADS 8
#define DH 32
#define MROWS (NSEQ*LL)         // 131072
#define SCALE 0.17677669529663687f

// ---------------- scratch (device globals; no cudaMalloc allowed) ----------
__device__ __nv_bfloat16 g_seq_hi[(size_t)MROWS * CC];
__device__ __nv_bfloat16 g_seq_lo[(size_t)MROWS * CC];
__device__ float         g_qkv   [(size_t)MROWS * 3 * CC];
__device__ __nv_bfloat16 g_att_hi[(size_t)MROWS * CC];
__device__ __nv_bfloat16 g_att_lo[(size_t)MROWS * CC];
__device__ float         g_proj  [(size_t)MROWS * CC];
// transposed + split weights: WT[n][k]
__device__ __nv_bfloat16 g_WqkvT_hi[3 * CC * CC];
__device__ __nv_bfloat16 g_WqkvT_lo[3 * CC * CC];
__device__ __nv_bfloat16 g_WoutT_hi[CC * CC];
__device__ __nv_bfloat16 g_WoutT_lo[CC * CC];

// ======================= baseline-PTX helpers (sm_80+) =====================
__device__ __forceinline__ uint32_t smem_u32(const void* p) {
    uint32_t a;
    asm("{ .reg .u64 t; cvta.to.shared.u64 t, %1; cvt.u32.u64 %0, t; }"
        : "=r"(a) : "l"(p));
    return a;
}
#define LDMX4(r0, r1, r2, r3, addr) \
    asm volatile("ldmatrix.sync.aligned.m8n8.x4.shared.b16 {%0,%1,%2,%3}, [%4];" \
                 : "=r"(r0), "=r"(r1), "=r"(r2), "=r"(r3) : "r"(addr))
#define MMA16816(d, a, b) \
    asm volatile("mma.sync.aligned.m16n8k16.row.col.f32.bf16.bf16.f32 " \
                 "{%0,%1,%2,%3}, {%4,%5,%6,%7}, {%8,%9}, {%0,%1,%2,%3};" \
                 : "+f"((d)[0]), "+f"((d)[1]), "+f"((d)[2]), "+f"((d)[3]) \
                 : "r"((a)[0]), "r"((a)[1]), "r"((a)[2]), "r"((a)[3]), \
                   "r"((b)[0]), "r"((b)[1]))
#define SW128(off) ((off) ^ (((off) >> 3) & 0x70))

__device__ __forceinline__ uint32_t pk_bf16x2(float e0, float e1) {
    return (uint32_t)__bfloat16_as_ushort(__float2bfloat16(e0)) |
           ((uint32_t)__bfloat16_as_ushort(__float2bfloat16(e1)) << 16);
}
__device__ __forceinline__ float bf_res(float v) {
    return v - __bfloat162float(__float2bfloat16(v));
}

// ---------------------------------------------------------------------------
// Kernel 1: gather/transpose  x(B,T,C,H,W) -> seq_hi/lo[(bt*W+w), h, c] (bf16)
// ---------------------------------------------------------------------------
__global__ void gather_seq_kernel(const float* __restrict__ x) {
    __shared__ float tile[32][33];
    const int bt = blockIdx.z >> 7;
    const int h  = blockIdx.z & 127;
    const int wbase = blockIdx.x * 32;
    const int cbase = blockIdx.y * 32;
    const int tx = threadIdx.x, ty = threadIdx.y;

    const float* xb = x + (size_t)bt * CC * HH * WW + (size_t)h * WW;
#pragma unroll
    for (int i = 0; i < 4; i++) {
        int c = cbase + ty + i * 8;
        tile[ty + i * 8][tx] = xb[(size_t)c * (HH * WW) + wbase + tx];
    }
    __syncthreads();
#pragma unroll
    for (int i = 0; i < 4; i++) {
        int w = wbase + ty + i * 8;
        float v = tile[tx][ty + i * 8];
        __nv_bfloat16 hi = __float2bfloat16(v);
        float lo = v - __bfloat162float(hi);
        size_t idx = ((size_t)(bt * WW + w) * LL + h) * CC + cbase + tx;
        g_seq_hi[idx] = hi;
        g_seq_lo[idx] = __float2bfloat16(lo);
    }
}

// ---------------------------------------------------------------------------
// Kernel 1b: weight prep — transpose + bf16 split.  WT[n][k] = W[k][n]
// ---------------------------------------------------------------------------
__global__ void wprep_kernel(const float* __restrict__ Wqkv,
                             const float* __restrict__ Wout) {
    int i = blockIdx.x * 256 + threadIdx.x;
    const int NQ = 3 * CC;
    if (i < NQ * CC) {
        int n = i / CC, k = i % CC;
        float v = Wqkv[(size_t)k * NQ + n];
        __nv_bfloat16 hi = __float2bfloat16(v);
        g_WqkvT_hi[(size_t)n * CC + k] = hi;
        g_WqkvT_lo[(size_t)n * CC + k] = __float2bfloat16(v - __bfloat162float(hi));
    }
    if (i < CC * CC) {
        int n = i / CC, k = i % CC;
        float v = Wout[(size_t)k * CC + n];
        __nv_bfloat16 hi = __float2bfloat16(v);
        g_WoutT_hi[(size_t)n * CC + k] = hi;
        g_WoutT_lo[(size_t)n * CC + k] = __float2bfloat16(v - __bfloat162float(hi));
    }
}

// ---------------------------------------------------------------------------
// Kernels 2 & 4: mma.sync bf16x3 GEMM (unchanged from round 4)
// ---------------------------------------------------------------------------
#define GK 256
#define KC 64
#define TILE_BYTES 16384
#define GEMM_SMEM (4 * TILE_BYTES)

__global__ __launch_bounds__(256)
void gemm_mma_kernel(const __nv_bfloat16* __restrict__ Ahi,
                     const __nv_bfloat16* __restrict__ Alo,
                     const __nv_bfloat16* __restrict__ Bhi,
                     const __nv_bfloat16* __restrict__ Blo,
                     const float* __restrict__ bias,
                     float* __restrict__ Cm, int N) {
    extern __shared__ char smc[];
    char* t_ahi = smc;
    char* t_alo = smc + TILE_BYTES;
    char* t_bhi = smc + 2 * TILE_BYTES;
    char* t_blo = smc + 3 * TILE_BYTES;
    const uint32_t s_ahi = smem_u32(t_ahi);
    const uint32_t s_alo = smem_u32(t_alo);
    const uint32_t s_bhi = smem_u32(t_bhi);
    const uint32_t s_blo = smem_u32(t_blo);

    const int tid = threadIdx.x;
    const int wid = tid >> 5;
    const int lid = tid & 31;
    const int mBase = blockIdx.y * 128;
    const int nBase = blockIdx.x * 128;
    const int wm = (wid & 1) * 64;
    const int wn = (wid >> 1) * 32;

    const int trow  = tid >> 1;
    const int thalf = (tid & 1) * 32;

    const int lr = lid & 7;
    const int lt = lid >> 3;
    const uint32_t a_off0 = (uint32_t)( (lr + (lt & 1) * 8) * 128 + ((lt >> 1) * 8) * 2 );
    const uint32_t b_off0 = (uint32_t)( (lr + (lt >> 1) * 8) * 128 + ((lt & 1) * 8) * 2 );

    float d[4][4][4];
#pragma unroll
    for (int i = 0; i < 4; i++)
#pragma unroll
        for (int j = 0; j < 4; j++)
#pragma unroll
            for (int r = 0; r < 4; r++) d[i][j][r] = 0.f;

    for (int c = 0; c < 4; c++) {
        const int k0 = c * KC;
        {
            const size_t arow = (size_t)(mBase + trow) * GK + k0 + thalf;
            const size_t brow = (size_t)(nBase + trow) * GK + k0 + thalf;
            const uint4* pAh = (const uint4*)(Ahi + arow);
            const uint4* pAl = (const uint4*)(Alo + arow);
            const uint4* pBh = (const uint4*)(Bhi + brow);
            const uint4* pBl = (const uint4*)(Blo + brow);
            const uint32_t ob = trow * 128 + thalf * 2;
#pragma unroll
            for (int i = 0; i < 4; i++) {
                const uint32_t sw = SW128(ob + i * 16);
                *(uint4*)(t_ahi + sw) = pAh[i];
                *(uint4*)(t_alo + sw) = pAl[i];
                *(uint4*)(t_bhi + sw) = pBh[i];
                *(uint4*)(t_blo + sw) = pBl[i];
            }
        }
        __syncthreads();

#pragma unroll
        for (int ks = 0; ks < 4; ks++) {
            const uint32_t kb = ks * 32;
            uint32_t ah[4][4], al[4][4], bh[4][2], bl[4][2];
#pragma unroll
            for (int mi = 0; mi < 4; mi++) {
                const uint32_t off = SW128(a_off0 + (wm + mi * 16) * 128 + kb);
                LDMX4(ah[mi][0], ah[mi][1], ah[mi][2], ah[mi][3], s_ahi + off);
                LDMX4(al[mi][0], al[mi][1], al[mi][2], al[mi][3], s_alo + off);
            }
#pragma unroll
            for (int ng = 0; ng < 2; ng++) {
                const uint32_t off = SW128(b_off0 + (wn + ng * 16) * 128 + kb);
                uint32_t r0, r1, r2, r3;
                LDMX4(r0, r1, r2, r3, s_bhi + off);
                bh[ng * 2][0] = r0; bh[ng * 2][1] = r1;
                bh[ng * 2 + 1][0] = r2; bh[ng * 2 + 1][1] = r3;
                LDMX4(r0, r1, r2, r3, s_blo + off);
                bl[ng * 2][0] = r0; bl[ng * 2][1] = r1;
                bl[ng * 2 + 1][0] = r2; bl[ng * 2 + 1][1] = r3;
            }
#pragma unroll
            for (int mi = 0; mi < 4; mi++)
#pragma unroll
                for (int nj = 0; nj < 4; nj++) {
                    MMA16816(d[mi][nj], ah[mi], bh[nj]);
                    MMA16816(d[mi][nj], ah[mi], bl[nj]);
                    MMA16816(d[mi][nj], al[mi], bh[nj]);
                }
        }
        __syncthreads();
    }

    const int erow = lid >> 2;
    const int ecol = (lid & 3) * 2;
#pragma unroll
    for (int nj = 0; nj < 4; nj++) {
        const int ncol = nBase + wn + nj * 8 + ecol;
        const float bx = bias[ncol], by = bias[ncol + 1];
#pragma unroll
        for (int mi = 0; mi < 4; mi++) {
            const int r0 = mBase + wm + mi * 16 + erow;
            float2 v0 = make_float2(d[mi][nj][0] + bx, d[mi][nj][1] + by);
            float2 v1 = make_float2(d[mi][nj][2] + bx, d[mi][nj][3] + by);
            *(float2*)&Cm[(size_t)r0 * N + ncol]       = v0;
            *(float2*)&Cm[(size_t)(r0 + 8) * N + ncol] = v1;
        }
    }
}

// ---------------------------------------------------------------------------
// Kernel 3: tensor-core attention.  CTA = (n, head, half); 64 q-rows x 128 keys.
// 8 warps = 4 l-groups(16 rows) x 2 m-halves(64 keys).
// smem tiles (128B rows, XOR-16B swizzle == SW128 of row*128+byte):
//   smq [64 rows][hi 0-31 | lo 32-63 bf16]   8 KB  (q, pre-scaled)
//   smk [128 rows][hi | lo]                 16 KB  (k; rows = key m)
//   smv [128 rows][64 bf16]                 16 KB  (vT: row = hl*64 + mh*32 + d,
//                                                   col = m_local 0..63)
//   red max/sum [2][64] each                 1 KB
//   obuf (aliases smq after S-phase)         8 KB
// ---------------------------------------------------------------------------
__global__ __launch_bounds__(256, 2)
void attention_mma_kernel(const float* __restrict__ rel_bias) {
    __shared__ __align__(128) char smq[8192];
    __shared__ __align__(128) char smk[16384];
    __shared__ __align__(128) char smv[16384];
    __shared__ float redmax[2][64];
    __shared__ float redsum[2][64];
    float* obuf = (float*)smq;

    const int bx = blockIdx.x;
    const int n  = bx >> 4;
    const int h  = (bx >> 1) & 7;
    const int half = bx & 1;
    const int l0 = half * 64;

    const int tid  = threadIdx.x;
    const int wid  = tid >> 5;
    const int lane = tid & 31;
    const int g    = wid >> 1;         // l-group 0..3
    const int mh   = wid & 1;          // m-half 0..1
    const int lr   = lane & 7;
    const int lt   = lane >> 3;
    const int r    = lane >> 2;        // 0..7
    const int cq   = (lane & 3) * 2;   // col pair base

    const uint32_t s_q = smem_u32(smq);
    const uint32_t s_k = smem_u32(smk);
    const uint32_t s_v = smem_u32(smv);

    const float* qkvb = g_qkv + (size_t)n * LL * (3 * CC) + h * DH;

    // ---- load + convert q (scaled), k, vT into hi|lo bf16 tiles ----
    {
        // q: 64 rows; thread -> (row, 8-elem group)
        int row = tid >> 2;
        int dq  = (tid & 3) * 8;
        const float* p = qkvb + (size_t)(l0 + row) * (3 * CC) + dq;
        float4 v0 = *(const float4*)p;
        float4 v1 = *(const float4*)(p + 4);
        float e[8] = {v0.x, v0.y, v0.z, v0.w, v1.x, v1.y, v1.z, v1.w};
#pragma unroll
        for (int i = 0; i < 8; i++) e[i] *= SCALE;
        uint4 hi4, lo4;
        hi4.x = pk_bf16x2(e[0], e[1]); hi4.y = pk_bf16x2(e[2], e[3]);
        hi4.z = pk_bf16x2(e[4], e[5]); hi4.w = pk_bf16x2(e[6], e[7]);
        lo4.x = pk_bf16x2(bf_res(e[0]), bf_res(e[1]));
        lo4.y = pk_bf16x2(bf_res(e[2]), bf_res(e[3]));
        lo4.z = pk_bf16x2(bf_res(e[4]), bf_res(e[5]));
        lo4.w = pk_bf16x2(bf_res(e[6]), bf_res(e[7]));
        *(uint4*)(smq + SW128(row * 128 + dq * 2))      = hi4;
        *(uint4*)(smq + SW128(row * 128 + 64 + dq * 2)) = lo4;
    }
    {
        // k: 128 rows; thread -> (row, 16-elem half)
        int row = tid >> 1;
        int dk  = (tid & 1) * 16;
        const float* p = qkvb + CC + (size_t)row * (3 * CC) + dk;
        float e[16];
#pragma unroll
        for (int i = 0; i < 16; i += 4) {
            float4 v = *(const float4*)(p + i);
            e[i] = v.x; e[i+1] = v.y; e[i+2] = v.z; e[i+3] = v.w;
        }
#pragma unroll
        for (int c2 = 0; c2 < 2; c2++) {
            uint4 hi4, lo4;
            const float* ee = e + c2 * 8;
            hi4.x = pk_bf16x2(ee[0], ee[1]); hi4.y = pk_bf16x2(ee[2], ee[3]);
            hi4.z = pk_bf16x2(ee[4], ee[5]); hi4.w = pk_bf16x2(ee[6], ee[7]);
            lo4.x = pk_bf16x2(bf_res(ee[0]), bf_res(ee[1]));
            lo4.y = pk_bf16x2(bf_res(ee[2]), bf_res(ee[3]));
            lo4.z = pk_bf16x2(bf_res(ee[4]), bf_res(ee[5]));
            lo4.w = pk_bf16x2(bf_res(ee[6]), bf_res(ee[7]));
            *(uint4*)(smk + SW128(row * 128 + dk * 2 + c2 * 16))      = hi4;
            *(uint4*)(smk + SW128(row * 128 + 64 + dk * 2 + c2 * 16)) = lo4;
        }
    }
    {
        // vT: scatter; thread -> (m row, 16 d values)
        int m  = tid >> 1;
        int dv = (tid & 1) * 16;
        int vmh = m >> 6, ml = m & 63;
        const float* p = qkvb + 2 * CC + (size_t)m * (3 * CC) + dv;
#pragma unroll
        for (int i = 0; i < 16; i++) {
            float v = p[i];
            __nv_bfloat16 hb = __float2bfloat16(v);
            __nv_bfloat16 lb = __float2bfloat16(v - __bfloat162float(hb));
            int rh = vmh * 32 + dv + i;
            *(__nv_bfloat16*)(smv + SW128(rh * 128 + ml * 2))        = hb;
            *(__nv_bfloat16*)(smv + SW128((64 + rh) * 128 + ml * 2)) = lb;
        }
    }
    __syncthreads();

    const uint32_t a_off0 = (uint32_t)((lr + (lt & 1) * 8) * 128 + ((lt >> 1) * 8) * 2);
    const uint32_t b_off0 = (uint32_t)((lr + (lt >> 1) * 8) * 128 + ((lt & 1) * 8) * 2);

    // ---- S = q @ k^T (bf16x3) ; warp tile 16(l) x 64(m) ----
    float sacc[8][4];
#pragma unroll
    for (int j = 0; j < 8; j++)
#pragma unroll
        for (int c = 0; c < 4; c++) sacc[j][c] = 0.f;

#pragma unroll
    for (int ks = 0; ks < 2; ks++) {
        const uint32_t kb = ks * 32;
        uint32_t ah[4], al[4];
        LDMX4(ah[0], ah[1], ah[2], ah[3], s_q + SW128(a_off0 + (g * 16) * 128 + kb));
        LDMX4(al[0], al[1], al[2], al[3], s_q + SW128(a_off0 + (g * 16) * 128 + 64 + kb));
#pragma unroll
        for (int j = 0; j < 4; j++) {
            uint32_t bh[4], bl[4];
            LDMX4(bh[0], bh[1], bh[2], bh[3],
                  s_k + SW128(b_off0 + (mh * 64 + j * 16) * 128 + kb));
            LDMX4(bl[0], bl[1], bl[2], bl[3],
                  s_k + SW128(b_off0 + (mh * 64 + j * 16) * 128 + 64 + kb));
            MMA16816(sacc[2 * j],     ah, &bh[0]);
            MMA16816(sacc[2 * j],     ah, &bl[0]);
            MMA16816(sacc[2 * j],     al, &bh[0]);
            MMA16816(sacc[2 * j + 1], ah, &bh[2]);
            MMA16816(sacc[2 * j + 1], ah, &bl[2]);
            MMA16816(sacc[2 * j + 1], al, &bh[2]);
        }
    }

    // ---- add rel_bias ----
    {
        const float* rb = rel_bias + ((size_t)h * LL + (l0 + g * 16 + r)) * LL
                        + mh * 64 + cq;
#pragma unroll
        for (int j = 0; j < 8; j++) {
            float2 b0 = *(const float2*)(rb + j * 8);
            float2 b1 = *(const float2*)(rb + 8 * LL + j * 8);
            sacc[j][0] += b0.x; sacc[j][1] += b0.y;
            sacc[j][2] += b1.x; sacc[j][3] += b1.y;
        }
    }

    // ---- softmax over m (rows r, r+8), cross m-half via smem ----
    float mx0 = -1e30f, mx1 = -1e30f;
#pragma unroll
    for (int j = 0; j < 8; j++) {
        mx0 = fmaxf(mx0, fmaxf(sacc[j][0], sacc[j][1]));
        mx1 = fmaxf(mx1, fmaxf(sacc[j][2], sacc[j][3]));
    }
    mx0 = fmaxf(mx0, __shfl_xor_sync(0xffffffff, mx0, 1));
    mx0 = fmaxf(mx0, __shfl_xor_sync(0xffffffff, mx0, 2));
    mx1 = fmaxf(mx1, __shfl_xor_sync(0xffffffff, mx1, 1));
    mx1 = fmaxf(mx1, __shfl_xor_sync(0xffffffff, mx1, 2));
    if ((lane & 3) == 0) {
        redmax[mh][g * 16 + r]     = mx0;
        redmax[mh][g * 16 + r + 8] = mx1;
    }
    __syncthreads();
    mx0 = fmaxf(redmax[0][g * 16 + r],     redmax[1][g * 16 + r]);
    mx1 = fmaxf(redmax[0][g * 16 + r + 8], redmax[1][g * 16 + r + 8]);

    float sum0 = 0.f, sum1 = 0.f;
#pragma unroll
    for (int j = 0; j < 8; j++) {
        sacc[j][0] = __expf(sacc[j][0] - mx0);
        sacc[j][1] = __expf(sacc[j][1] - mx0);
        sacc[j][2] = __expf(sacc[j][2] - mx1);
        sacc[j][3] = __expf(sacc[j][3] - mx1);
        sum0 += sacc[j][0] + sacc[j][1];
        sum1 += sacc[j][2] + sacc[j][3];
    }
    sum0 += __shfl_xor_sync(0xffffffff, sum0, 1);
    sum0 += __shfl_xor_sync(0xffffffff, sum0, 2);
    sum1 += __shfl_xor_sync(0xffffffff, sum1, 1);
    sum1 += __shfl_xor_sync(0xffffffff, sum1, 2);
    if ((lane & 3) == 0) {
        redsum[mh][g * 16 + r]     = sum0;
        redsum[mh][g * 16 + r + 8] = sum1;
    }
    __syncthreads();
    const float inv0 = 1.f / (redsum[0][g * 16 + r]     + redsum[1][g * 16 + r]);
    const float inv1 = 1.f / (redsum[0][g * 16 + r + 8] + redsum[1][g * 16 + r + 8]);

    // ---- convert P fragments (C-frag -> A-frag identity), hi/lo ----
    uint32_t phi[8][2], plo[8][2];
#pragma unroll
    for (int j = 0; j < 8; j++) {
        phi[j][0] = pk_bf16x2(sacc[j][0], sacc[j][1]);
        phi[j][1] = pk_bf16x2(sacc[j][2], sacc[j][3]);
        plo[j][0] = pk_bf16x2(bf_res(sacc[j][0]), bf_res(sacc[j][1]));
        plo[j][1] = pk_bf16x2(bf_res(sacc[j][2]), bf_res(sacc[j][3]));
    }

    // ---- O(partial) = P @ V over this warp's m-half ----
    float oacc[4][4];
#pragma unroll
    for (int dg = 0; dg < 4; dg++)
#pragma unroll
        for (int c = 0; c < 4; c++) oacc[dg][c] = 0.f;

#pragma unroll
    for (int t = 0; t < 4; t++) {
        uint32_t a_h[4] = { phi[2 * t][0], phi[2 * t][1],
                            phi[2 * t + 1][0], phi[2 * t + 1][1] };
        uint32_t a_l[4] = { plo[2 * t][0], plo[2 * t][1],
                            plo[2 * t + 1][0], plo[2 * t + 1][1] };
        uint32_t bh[8], bl[8];
        LDMX4(bh[0], bh[1], bh[2], bh[3],
              s_v + SW128(b_off0 + (mh * 32) * 128 + t * 32));
        LDMX4(bh[4], bh[5], bh[6], bh[7],
              s_v + SW128(b_off0 + (mh * 32 + 16) * 128 + t * 32));
        LDMX4(bl[0], bl[1], bl[2], bl[3],
              s_v + SW128(b_off0 + (64 + mh * 32) * 128 + t * 32));
        LDMX4(bl[4], bl[5], bl[6], bl[7],
              s_v + SW128(b_off0 + (64 + mh * 32 + 16) * 128 + t * 32));
#pragma unroll
        for (int dg = 0; dg < 4; dg++) {
            MMA16816(oacc[dg], a_h, &bh[dg * 2]);
            MMA16816(oacc[dg], a_l, &bh[dg * 2]);
            MMA16816(oacc[dg], a_h, &bl[dg * 2]);
        }
    }

    // ---- cross-warp O sum (obuf aliases smq; q is dead) + store ----
    if (mh == 1) {
#pragma unroll
        for (int dg = 0; dg < 4; dg++) {
            *(float2*)&obuf[g * 512 + r * 32 + dg * 8 + cq] =
                make_float2(oacc[dg][0], oacc[dg][1]);
            *(float2*)&obuf[g * 512 + (r + 8) * 32 + dg * 8 + cq] =
                make_float2(oacc[dg][2], oacc[dg][3]);
        }
    }
    __syncthreads();
    if (mh == 0) {
        const int row0 = n * LL + l0 + g * 16 + r;
#pragma unroll
        for (int dg = 0; dg < 4; dg++) {
            float2 q0 = *(float2*)&obuf[g * 512 + r * 32 + dg * 8 + cq];
            float2 q1 = *(float2*)&obuf[g * 512 + (r + 8) * 32 + dg * 8 + cq];
            float o0 = (oacc[dg][0] + q0.x) * inv0;
            float o1 = (oacc[dg][1] + q0.y) * inv0;
            float o2 = (oacc[dg][2] + q1.x) * inv1;
            float o3 = (oacc[dg][3] + q1.y) * inv1;
            size_t off0 = (size_t)row0 * CC + h * DH + dg * 8 + cq;
            size_t off1 = (size_t)(row0 + 8) * CC + h * DH + dg * 8 + cq;
            *(uint32_t*)&g_att_hi[off0] = pk_bf16x2(o0, o1);
            *(uint32_t*)&g_att_lo[off0] = pk_bf16x2(bf_res(o0), bf_res(o1));
            *(uint32_t*)&g_att_hi[off1] = pk_bf16x2(o2, o3);
            *(uint32_t*)&g_att_lo[off1] = pk_bf16x2(bf_res(o2), bf_res(o3));
        }
    }
}

// ---------------------------------------------------------------------------
// Kernel 5: scatter/transpose  proj[(bt*W+w), h, c] -> out(B,T,C,H,W)
// ---------------------------------------------------------------------------
__global__ void scatter_out_kernel(float* __restrict__ out) {
    __shared__ float tile[32][33];
    const int bt = blockIdx.z >> 7;
    const int h  = blockIdx.z & 127;
    const int wbase = blockIdx.x * 32;
    const int cbase = blockIdx.y * 32;
    const int tx = threadIdx.x, ty = threadIdx.y;

#pragma unroll
    for (int i = 0; i < 4; i++) {
        int w = wbase + ty + i * 8;
        tile[ty + i * 8][tx] = g_proj[((size_t)(bt * WW + w) * LL + h) * CC + cbase + tx];
    }
    __syncthreads();
    float* ob = out + (size_t)bt * CC * HH * WW + (size_t)h * WW;
#pragma unroll
    for (int i = 0; i < 4; i++) {
        int c = cbase + ty + i * 8;
        ob[(size_t)c * (HH * WW) + wbase + tx] = tile[tx][ty + i * 8];
    }
}

// ---------------------------------------------------------------------------
extern "C" void kernel_launch(void* const* d_in, const int* in_sizes, int n_in,
                              void* d_out, int out_size) {
    const float* x        = (const float*)d_in[0];
    const float* rel_bias = (const float*)d_in[1];
    const float* Wqkv     = (const float*)d_in[2];
    const float* bqkv     = (const float*)d_in[3];
    const float* Wout     = (const float*)d_in[4];
    const float* bout     = (const float*)d_in[5];
    float* out = (float*)d_out;

    void *p_qkv, *p_proj;
    void *p_shi, *p_slo, *p_ahi, *p_alo;
    void *p_wqh, *p_wql, *p_woh, *p_wol;
    cudaGetSymbolAddress(&p_qkv,  g_qkv);
    cudaGetSymbolAddress(&p_proj, g_proj);
    cudaGetSymbolAddress(&p_shi, g_seq_hi);
    cudaGetSymbolAddress(&p_slo, g_seq_lo);
    cudaGetSymbolAddress(&p_ahi, g_att_hi);
    cudaGetSymbolAddress(&p_alo, g_att_lo);
    cudaGetSymbolAddress(&p_wqh, g_WqkvT_hi);
    cudaGetSymbolAddress(&p_wql, g_WqkvT_lo);
    cudaGetSymbolAddress(&p_woh, g_WoutT_hi);
    cudaGetSymbolAddress(&p_wol, g_WoutT_lo);

    cudaFuncSetAttribute(gemm_mma_kernel,
                         cudaFuncAttributeMaxDynamicSharedMemorySize,
                         GEMM_SMEM);

    // 1) gather x -> seq hi/lo (bf16 split)
    gather_seq_kernel<<<dim3(WW / 32, CC / 32, BT * HH), dim3(32, 8)>>>(x);

    // 1b) weight transpose + split
    wprep_kernel<<<(3 * CC * CC + 255) / 256, 256>>>(Wqkv, Wout);

    // 2) qkv = seq @ Wqkv + bqkv   (mma.sync bf16x3)
    gemm_mma_kernel<<<dim3(3 * CC / 128, MROWS / 128), 256, GEMM_SMEM>>>(
        (const __nv_bfloat16*)p_shi, (const __nv_bfloat16*)p_slo,
        (const __nv_bfloat16*)p_wqh, (const __nv_bfloat16*)p_wql,
        bqkv, (float*)p_qkv, 3 * CC);

    // 3) attention (tensor-core), CTA = (n, head, half)
    attention_mma_kernel<<<NSEQ * HEADS * 2, 256>>>(rel_bias);

    // 4) proj = att @ Wout + bout  (mma.sync bf16x3)
    gemm_mma_kernel<<<dim3(CC / 128, MROWS / 128), 256, GEMM_SMEM>>>(
        (const __nv_bfloat16*)p_ahi, (const __nv_bfloat16*)p_alo,
        (const __nv_bfloat16*)p_woh, (const __nv_bfloat16*)p_wol,
        bout, (float*)p_proj, CC);

    // 5) scatter proj -> out
    scatter_out_kernel<<<dim3(WW / 32, CC / 32, BT * HH), dim3(32, 8)>>>(out);
}

// round 8
// speedup vs baseline: 1.7948x; 1.1234x over previous
#include <cuda_runtime.h>
#include <cuda_bf16.h>
#include <cstdint>

// Problem constants
#define BB 2
#define TT 4
#define CC 256
#define HH 128
#define WW 128
#define BT (BB*TT)              // 8
#define NSEQ (BT*WW)            // 1024
#define LL HH                   // 128
#define HEADS 8
#define DH 32
#define MROWS (NSEQ*LL)         // 131072
#define SCALE 0.17677669529663687f

// ---------------- scratch (device globals; no cudaMalloc allowed) ----------
__device__ __nv_bfloat16 g_seq_hi[(size_t)MROWS * CC];
__device__ __nv_bfloat16 g_seq_lo[(size_t)MROWS * CC];
__device__ float         g_qkv   [(size_t)MROWS * 3 * CC];
__device__ __nv_bfloat16 g_att_hi[(size_t)MROWS * CC];
__device__ __nv_bfloat16 g_att_lo[(size_t)MROWS * CC];
__device__ float         g_proj  [(size_t)MROWS * CC];
// transposed + split weights: WT[n][k]
__device__ __nv_bfloat16 g_WqkvT_hi[3 * CC * CC];
__device__ __nv_bfloat16 g_WqkvT_lo[3 * CC * CC];
__device__ __nv_bfloat16 g_WoutT_hi[CC * CC];
__device__ __nv_bfloat16 g_WoutT_lo[CC * CC];

// ======================= baseline-PTX helpers (sm_80+) =====================
__device__ __forceinline__ uint32_t smem_u32(const void* p) {
    uint32_t a;
    asm("{ .reg .u64 t; cvta.to.shared.u64 t, %1; cvt.u32.u64 %0, t; }"
        : "=r"(a) : "l"(p));
    return a;
}
#define LDMX4(r0, r1, r2, r3, addr) \
    asm volatile("ldmatrix.sync.aligned.m8n8.x4.shared.b16 {%0,%1,%2,%3}, [%4];" \
                 : "=r"(r0), "=r"(r1), "=r"(r2), "=r"(r3) : "r"(addr))
#define LDMX4T(r0, r1, r2, r3, addr) \
    asm volatile("ldmatrix.sync.aligned.m8n8.x4.trans.shared.b16 {%0,%1,%2,%3}, [%4];" \
                 : "=r"(r0), "=r"(r1), "=r"(r2), "=r"(r3) : "r"(addr))
#define MMA16816(d, a, b) \
    asm volatile("mma.sync.aligned.m16n8k16.row.col.f32.bf16.bf16.f32 " \
                 "{%0,%1,%2,%3}, {%4,%5,%6,%7}, {%8,%9}, {%0,%1,%2,%3};" \
                 : "+f"((d)[0]), "+f"((d)[1]), "+f"((d)[2]), "+f"((d)[3]) \
                 : "r"((a)[0]), "r"((a)[1]), "r"((a)[2]), "r"((a)[3]), \
                   "r"((b)[0]), "r"((b)[1]))
#define SW128(off) ((off) ^ (((off) >> 3) & 0x70))

#define CP16(dst, src) \
    asm volatile("cp.async.cg.shared.global [%0], [%1], 16;" :: "r"(dst), "l"(src))
#define CP_COMMIT() asm volatile("cp.async.commit_group;" ::: "memory")
#define CP_WAIT1()  asm volatile("cp.async.wait_group 1;" ::: "memory")
#define CP_WAIT0()  asm volatile("cp.async.wait_group 0;" ::: "memory")

__device__ __forceinline__ uint32_t pk_bf16x2(float e0, float e1) {
    return (uint32_t)__bfloat16_as_ushort(__float2bfloat16(e0)) |
           ((uint32_t)__bfloat16_as_ushort(__float2bfloat16(e1)) << 16);
}
__device__ __forceinline__ float bf_res(float v) {
    return v - __bfloat162float(__float2bfloat16(v));
}

// ---------------------------------------------------------------------------
// Kernel 1: gather/transpose  x(B,T,C,H,W) -> seq_hi/lo[(bt*W+w), h, c] (bf16)
// ---------------------------------------------------------------------------
__global__ void gather_seq_kernel(const float* __restrict__ x) {
    __shared__ float tile[32][33];
    const int bt = blockIdx.z >> 7;
    const int h  = blockIdx.z & 127;
    const int wbase = blockIdx.x * 32;
    const int cbase = blockIdx.y * 32;
    const int tx = threadIdx.x, ty = threadIdx.y;

    const float* xb = x + (size_t)bt * CC * HH * WW + (size_t)h * WW;
#pragma unroll
    for (int i = 0; i < 4; i++) {
        int c = cbase + ty + i * 8;
        tile[ty + i * 8][tx] = xb[(size_t)c * (HH * WW) + wbase + tx];
    }
    __syncthreads();
#pragma unroll
    for (int i = 0; i < 4; i++) {
        int w = wbase + ty + i * 8;
        float v = tile[tx][ty + i * 8];
        __nv_bfloat16 hi = __float2bfloat16(v);
        float lo = v - __bfloat162float(hi);
        size_t idx = ((size_t)(bt * WW + w) * LL + h) * CC + cbase + tx;
        g_seq_hi[idx] = hi;
        g_seq_lo[idx] = __float2bfloat16(lo);
    }
}

// ---------------------------------------------------------------------------
// Kernel 1b: weight prep — transpose + bf16 split.  WT[n][k] = W[k][n]
// ---------------------------------------------------------------------------
__global__ void wprep_kernel(const float* __restrict__ Wqkv,
                             const float* __restrict__ Wout) {
    int i = blockIdx.x * 256 + threadIdx.x;
    const int NQ = 3 * CC;
    if (i < NQ * CC) {
        int n = i / CC, k = i % CC;
        float v = Wqkv[(size_t)k * NQ + n];
        __nv_bfloat16 hi = __float2bfloat16(v);
        g_WqkvT_hi[(size_t)n * CC + k] = hi;
        g_WqkvT_lo[(size_t)n * CC + k] = __float2bfloat16(v - __bfloat162float(hi));
    }
    if (i < CC * CC) {
        int n = i / CC, k = i % CC;
        float v = Wout[(size_t)k * CC + n];
        __nv_bfloat16 hi = __float2bfloat16(v);
        g_WoutT_hi[(size_t)n * CC + k] = hi;
        g_WoutT_lo[(size_t)n * CC + k] = __float2bfloat16(v - __bfloat162float(hi));
    }
}

// ---------------------------------------------------------------------------
// Kernels 2 & 4: mma.sync bf16x3 GEMM with 2-stage cp.async pipeline.
// KC=32 per chunk; tile row = 128B = [hi 32 bf16 | lo 32 bf16]; A,B tiles 16KB.
// stage = A+B = 32KB; 2 stages = 64KB smem.
// ---------------------------------------------------------------------------
#define GK 256
#define KC2 32
#define ATILE 16384
#define STAGE (2 * ATILE)
#define GEMM_SMEM (2 * STAGE)

#define GEMM_PREFETCH(c) do {                                   \
    uint32_t _sa = s0 + ((c) & 1) * STAGE;                      \
    uint32_t _sb = _sa + ATILE;                                 \
    int _k0 = (c) * KC2;                                        \
    CP16(_sa + SW128(ld_off),      gAh + _k0);                  \
    CP16(_sa + SW128(ld_off + 16), gAh + _k0 + 8);              \
    CP16(_sa + SW128(ld_off + 64), gAl + _k0);                  \
    CP16(_sa + SW128(ld_off + 80), gAl + _k0 + 8);              \
    CP16(_sb + SW128(ld_off),      gBh + _k0);                  \
    CP16(_sb + SW128(ld_off + 16), gBh + _k0 + 8);              \
    CP16(_sb + SW128(ld_off + 64), gBl + _k0);                  \
    CP16(_sb + SW128(ld_off + 80), gBl + _k0 + 8);              \
    CP_COMMIT();                                                \
} while (0)

__global__ __launch_bounds__(256)
void gemm_mma_kernel(const __nv_bfloat16* __restrict__ Ahi,
                     const __nv_bfloat16* __restrict__ Alo,
                     const __nv_bfloat16* __restrict__ Bhi,
                     const __nv_bfloat16* __restrict__ Blo,
                     const float* __restrict__ bias,
                     float* __restrict__ Cm, int N) {
    extern __shared__ char smc[];
    const uint32_t s0 = smem_u32(smc);

    const int tid = threadIdx.x;
    const int wid = tid >> 5;
    const int lid = tid & 31;
    const int mBase = blockIdx.y * 128;
    const int nBase = blockIdx.x * 128;
    const int wm = (wid & 1) * 64;
    const int wn = (wid >> 1) * 32;

    // loader mapping: thread -> (row, 16-elem half of the 32-elem chunk)
    const int trow = tid >> 1;
    const int tp   = tid & 1;
    const uint32_t ld_off = (uint32_t)(trow * 128 + tp * 32);
    const __nv_bfloat16* gAh = Ahi + (size_t)(mBase + trow) * GK + tp * 16;
    const __nv_bfloat16* gAl = Alo + (size_t)(mBase + trow) * GK + tp * 16;
    const __nv_bfloat16* gBh = Bhi + (size_t)(nBase + trow) * GK + tp * 16;
    const __nv_bfloat16* gBl = Blo + (size_t)(nBase + trow) * GK + tp * 16;

    const int lr = lid & 7;
    const int lt = lid >> 3;
    const uint32_t a_off0 = (uint32_t)((lr + (lt & 1) * 8) * 128 + ((lt >> 1) * 8) * 2);
    const uint32_t b_off0 = (uint32_t)((lr + (lt >> 1) * 8) * 128 + ((lt & 1) * 8) * 2);

    float d[4][4][4];
#pragma unroll
    for (int i = 0; i < 4; i++)
#pragma unroll
        for (int j = 0; j < 4; j++)
#pragma unroll
            for (int r = 0; r < 4; r++) d[i][j][r] = 0.f;

    GEMM_PREFETCH(0);

    for (int c = 0; c < 8; c++) {
        if (c < 7) { GEMM_PREFETCH(c + 1); CP_WAIT1(); }
        else       { CP_WAIT0(); }
        __syncthreads();

        const uint32_t sa = s0 + (c & 1) * STAGE;
        const uint32_t sb = sa + ATILE;

#pragma unroll
        for (int ks = 0; ks < 2; ks++) {
            const uint32_t kb = ks * 32;
            uint32_t ah[4][4], al[4][4], bh[4][2], bl[4][2];
#pragma unroll
            for (int mi = 0; mi < 4; mi++) {
                const uint32_t off = a_off0 + (wm + mi * 16) * 128 + kb;
                LDMX4(ah[mi][0], ah[mi][1], ah[mi][2], ah[mi][3], sa + SW128(off));
                LDMX4(al[mi][0], al[mi][1], al[mi][2], al[mi][3], sa + SW128(off + 64));
            }
#pragma unroll
            for (int ng = 0; ng < 2; ng++) {
                const uint32_t off = b_off0 + (wn + ng * 16) * 128 + kb;
                uint32_t r0, r1, r2, r3;
                LDMX4(r0, r1, r2, r3, sb + SW128(off));
                bh[ng * 2][0] = r0; bh[ng * 2][1] = r1;
                bh[ng * 2 + 1][0] = r2; bh[ng * 2 + 1][1] = r3;
                LDMX4(r0, r1, r2, r3, sb + SW128(off + 64));
                bl[ng * 2][0] = r0; bl[ng * 2][1] = r1;
                bl[ng * 2 + 1][0] = r2; bl[ng * 2 + 1][1] = r3;
            }
#pragma unroll
            for (int mi = 0; mi < 4; mi++)
#pragma unroll
                for (int nj = 0; nj < 4; nj++) {
                    MMA16816(d[mi][nj], ah[mi], bh[nj]);
                    MMA16816(d[mi][nj], ah[mi], bl[nj]);
                    MMA16816(d[mi][nj], al[mi], bh[nj]);
                }
        }
        __syncthreads();
    }

    const int erow = lid >> 2;
    const int ecol = (lid & 3) * 2;
#pragma unroll
    for (int nj = 0; nj < 4; nj++) {
        const int ncol = nBase + wn + nj * 8 + ecol;
        const float bx = bias[ncol], by = bias[ncol + 1];
#pragma unroll
        for (int mi = 0; mi < 4; mi++) {
            const int r0 = mBase + wm + mi * 16 + erow;
            float2 v0 = make_float2(d[mi][nj][0] + bx, d[mi][nj][1] + by);
            float2 v1 = make_float2(d[mi][nj][2] + bx, d[mi][nj][3] + by);
            *(float2*)&Cm[(size_t)r0 * N + ncol]       = v0;
            *(float2*)&Cm[(size_t)(r0 + 8) * N + ncol] = v1;
        }
    }
}

// ---------------------------------------------------------------------------
// Kernel 3: tensor-core attention.  CTA = (n, head, half); 64 q-rows x 128 keys.
// 8 warps = 4 l-groups(16 rows) x 2 m-halves(64 keys).
// smq [64 rows][hi|lo]  8 KB ; smk [128 rows][hi|lo] 16 KB ;
// smv [128 rows][hi|lo] 16 KB (row = key m, like K; PV uses ldmatrix.trans)
// ---------------------------------------------------------------------------
__global__ __launch_bounds__(256, 2)
void attention_mma_kernel(const float* __restrict__ rel_bias) {
    __shared__ __align__(128) char smq[8192];
    __shared__ __align__(128) char smk[16384];
    __shared__ __align__(128) char smv[16384];
    __shared__ float redmax[2][64];
    __shared__ float redsum[2][64];
    float* obuf = (float*)smq;

    const int bx = blockIdx.x;
    const int n  = bx >> 4;
    const int h  = (bx >> 1) & 7;
    const int half = bx & 1;
    const int l0 = half * 64;

    const int tid  = threadIdx.x;
    const int wid  = tid >> 5;
    const int lane = tid & 31;
    const int g    = wid >> 1;         // l-group 0..3
    const int mh   = wid & 1;          // m-half 0..1
    const int lr   = lane & 7;
    const int lt   = lane >> 3;
    const int r    = lane >> 2;        // 0..7
    const int cq   = (lane & 3) * 2;   // col pair base

    const uint32_t s_q = smem_u32(smq);
    const uint32_t s_k = smem_u32(smk);
    const uint32_t s_v = smem_u32(smv);

    const float* qkvb = g_qkv + (size_t)n * LL * (3 * CC) + h * DH;

    // ---- load + convert q (scaled) ----
    {
        int row = tid >> 2;
        int dq  = (tid & 3) * 8;
        const float* p = qkvb + (size_t)(l0 + row) * (3 * CC) + dq;
        float4 v0 = *(const float4*)p;
        float4 v1 = *(const float4*)(p + 4);
        float e[8] = {v0.x, v0.y, v0.z, v0.w, v1.x, v1.y, v1.z, v1.w};
#pragma unroll
        for (int i = 0; i < 8; i++) e[i] *= SCALE;
        uint4 hi4, lo4;
        hi4.x = pk_bf16x2(e[0], e[1]); hi4.y = pk_bf16x2(e[2], e[3]);
        hi4.z = pk_bf16x2(e[4], e[5]); hi4.w = pk_bf16x2(e[6], e[7]);
        lo4.x = pk_bf16x2(bf_res(e[0]), bf_res(e[1]));
        lo4.y = pk_bf16x2(bf_res(e[2]), bf_res(e[3]));
        lo4.z = pk_bf16x2(bf_res(e[4]), bf_res(e[5]));
        lo4.w = pk_bf16x2(bf_res(e[6]), bf_res(e[7]));
        *(uint4*)(smq + SW128(row * 128 + dq * 2))      = hi4;
        *(uint4*)(smq + SW128(row * 128 + 64 + dq * 2)) = lo4;
    }
    // ---- load + convert k and v (identical row layout) ----
    {
        int row = tid >> 1;
        int dk  = (tid & 1) * 16;
#pragma unroll
        for (int src = 0; src < 2; src++) {   // 0: k, 1: v
            const float* p = qkvb + (src + 1) * CC + (size_t)row * (3 * CC) + dk;
            char* dst = src ? smv : smk;
            float e[16];
#pragma unroll
            for (int i = 0; i < 16; i += 4) {
                float4 v = *(const float4*)(p + i);
                e[i] = v.x; e[i+1] = v.y; e[i+2] = v.z; e[i+3] = v.w;
            }
#pragma unroll
            for (int c2 = 0; c2 < 2; c2++) {
                uint4 hi4, lo4;
                const float* ee = e + c2 * 8;
                hi4.x = pk_bf16x2(ee[0], ee[1]); hi4.y = pk_bf16x2(ee[2], ee[3]);
                hi4.z = pk_bf16x2(ee[4], ee[5]); hi4.w = pk_bf16x2(ee[6], ee[7]);
                lo4.x = pk_bf16x2(bf_res(ee[0]), bf_res(ee[1]));
                lo4.y = pk_bf16x2(bf_res(ee[2]), bf_res(ee[3]));
                lo4.z = pk_bf16x2(bf_res(ee[4]), bf_res(ee[5]));
                lo4.w = pk_bf16x2(bf_res(ee[6]), bf_res(ee[7]));
                *(uint4*)(dst + SW128(row * 128 + dk * 2 + c2 * 16))      = hi4;
                *(uint4*)(dst + SW128(row * 128 + 64 + dk * 2 + c2 * 16)) = lo4;
            }
        }
    }
    __syncthreads();

    const uint32_t a_off0 = (uint32_t)((lr + (lt & 1) * 8) * 128 + ((lt >> 1) * 8) * 2);
    const uint32_t b_off0 = (uint32_t)((lr + (lt >> 1) * 8) * 128 + ((lt & 1) * 8) * 2);

    // ---- S = q @ k^T (bf16x3) ; warp tile 16(l) x 64(m) ----
    float sacc[8][4];
#pragma unroll
    for (int j = 0; j < 8; j++)
#pragma unroll
        for (int c = 0; c < 4; c++) sacc[j][c] = 0.f;

#pragma unroll
    for (int ks = 0; ks < 2; ks++) {
        const uint32_t kb = ks * 32;
        uint32_t ah[4], al[4];
        LDMX4(ah[0], ah[1], ah[2], ah[3], s_q + SW128(a_off0 + (g * 16) * 128 + kb));
        LDMX4(al[0], al[1], al[2], al[3], s_q + SW128(a_off0 + (g * 16) * 128 + 64 + kb));
#pragma unroll
        for (int j = 0; j < 4; j++) {
            uint32_t bh[4], bl[4];
            LDMX4(bh[0], bh[1], bh[2], bh[3],
                  s_k + SW128(b_off0 + (mh * 64 + j * 16) * 128 + kb));
            LDMX4(bl[0], bl[1], bl[2], bl[3],
                  s_k + SW128(b_off0 + (mh * 64 + j * 16) * 128 + 64 + kb));
            MMA16816(sacc[2 * j],     ah, &bh[0]);
            MMA16816(sacc[2 * j],     ah, &bl[0]);
            MMA16816(sacc[2 * j],     al, &bh[0]);
            MMA16816(sacc[2 * j + 1], ah, &bh[2]);
            MMA16816(sacc[2 * j + 1], ah, &bl[2]);
            MMA16816(sacc[2 * j + 1], al, &bh[2]);
        }
    }

    // ---- add rel_bias ----
    {
        const float* rb = rel_bias + ((size_t)h * LL + (l0 + g * 16 + r)) * LL
                        + mh * 64 + cq;
#pragma unroll
        for (int j = 0; j < 8; j++) {
            float2 b0 = *(const float2*)(rb + j * 8);
            float2 b1 = *(const float2*)(rb + 8 * LL + j * 8);
            sacc[j][0] += b0.x; sacc[j][1] += b0.y;
            sacc[j][2] += b1.x; sacc[j][3] += b1.y;
        }
    }

    // ---- softmax over m (rows r, r+8), cross m-half via smem ----
    float mx0 = -1e30f, mx1 = -1e30f;
#pragma unroll
    for (int j = 0; j < 8; j++) {
        mx0 = fmaxf(mx0, fmaxf(sacc[j][0], sacc[j][1]));
        mx1 = fmaxf(mx1, fmaxf(sacc[j][2], sacc[j][3]));
    }
    mx0 = fmaxf(mx0, __shfl_xor_sync(0xffffffff, mx0, 1));
    mx0 = fmaxf(mx0, __shfl_xor_sync(0xffffffff, mx0, 2));
    mx1 = fmaxf(mx1, __shfl_xor_sync(0xffffffff, mx1, 1));
    mx1 = fmaxf(mx1, __shfl_xor_sync(0xffffffff, mx1, 2));
    if ((lane & 3) == 0) {
        redmax[mh][g * 16 + r]     = mx0;
        redmax[mh][g * 16 + r + 8] = mx1;
    }
    __syncthreads();
    mx0 = fmaxf(redmax[0][g * 16 + r],     redmax[1][g * 16 + r]);
    mx1 = fmaxf(redmax[0][g * 16 + r + 8], redmax[1][g * 16 + r + 8]);

    float sum0 = 0.f, sum1 = 0.f;
#pragma unroll
    for (int j = 0; j < 8; j++) {
        sacc[j][0] = __expf(sacc[j][0] - mx0);
        sacc[j][1] = __expf(sacc[j][1] - mx0);
        sacc[j][2] = __expf(sacc[j][2] - mx1);
        sacc[j][3] = __expf(sacc[j][3] - mx1);
        sum0 += sacc[j][0] + sacc[j][1];
        sum1 += sacc[j][2] + sacc[j][3];
    }
    sum0 += __shfl_xor_sync(0xffffffff, sum0, 1);
    sum0 += __shfl_xor_sync(0xffffffff, sum0, 2);
    sum1 += __shfl_xor_sync(0xffffffff, sum1, 1);
    sum1 += __shfl_xor_sync(0xffffffff, sum1, 2);
    if ((lane & 3) == 0) {
        redsum[mh][g * 16 + r]     = sum0;
        redsum[mh][g * 16 + r + 8] = sum1;
    }
    __syncthreads();
    const float inv0 = 1.f / (redsum[0][g * 16 + r]     + redsum[1][g * 16 + r]);
    const float inv1 = 1.f / (redsum[0][g * 16 + r + 8] + redsum[1][g * 16 + r + 8]);

    // ---- convert P fragments (C-frag -> A-frag identity), hi/lo ----
    uint32_t phi[8][2], plo[8][2];
#pragma unroll
    for (int j = 0; j < 8; j++) {
        phi[j][0] = pk_bf16x2(sacc[j][0], sacc[j][1]);
        phi[j][1] = pk_bf16x2(sacc[j][2], sacc[j][3]);
        plo[j][0] = pk_bf16x2(bf_res(sacc[j][0]), bf_res(sacc[j][1]));
        plo[j][1] = pk_bf16x2(bf_res(sacc[j][2]), bf_res(sacc[j][3]));
    }

    // ---- O(partial) = P @ V over this warp's m-half (ldmatrix.trans B) ----
    float oacc[4][4];
#pragma unroll
    for (int dg = 0; dg < 4; dg++)
#pragma unroll
        for (int c = 0; c < 4; c++) oacc[dg][c] = 0.f;

#pragma unroll
    for (int t = 0; t < 4; t++) {
        const uint32_t vrow = (uint32_t)(mh * 64 + t * 16) * 128;
        uint32_t a_h[4] = { phi[2 * t][0], phi[2 * t][1],
                            phi[2 * t + 1][0], phi[2 * t + 1][1] };
        uint32_t a_l[4] = { plo[2 * t][0], plo[2 * t][1],
                            plo[2 * t + 1][0], plo[2 * t + 1][1] };
        uint32_t bh[8], bl[8];
        LDMX4T(bh[0], bh[1], bh[2], bh[3], s_v + SW128(a_off0 + vrow + 0));
        LDMX4T(bh[4], bh[5], bh[6], bh[7], s_v + SW128(a_off0 + vrow + 32));
        LDMX4T(bl[0], bl[1], bl[2], bl[3], s_v + SW128(a_off0 + vrow + 64));
        LDMX4T(bl[4], bl[5], bl[6], bl[7], s_v + SW128(a_off0 + vrow + 96));
#pragma unroll
        for (int dg = 0; dg < 4; dg++) {
            MMA16816(oacc[dg], a_h, &bh[dg * 2]);
            MMA16816(oacc[dg], a_l, &bh[dg * 2]);
            MMA16816(oacc[dg], a_h, &bl[dg * 2]);
        }
    }

    // ---- cross-warp O sum (obuf aliases smq; q is dead) + store ----
    if (mh == 1) {
#pragma unroll
        for (int dg = 0; dg < 4; dg++) {
            *(float2*)&obuf[g * 512 + r * 32 + dg * 8 + cq] =
                make_float2(oacc[dg][0], oacc[dg][1]);
            *(float2*)&obuf[g * 512 + (r + 8) * 32 + dg * 8 + cq] =
                make_float2(oacc[dg][2], oacc[dg][3]);
        }
    }
    __syncthreads();
    if (mh == 0) {
        const int row0 = n * LL + l0 + g * 16 + r;
#pragma unroll
        for (int dg = 0; dg < 4; dg++) {
            float2 q0 = *(float2*)&obuf[g * 512 + r * 32 + dg * 8 + cq];
            float2 q1 = *(float2*)&obuf[g * 512 + (r + 8) * 32 + dg * 8 + cq];
            float o0 = (oacc[dg][0] + q0.x) * inv0;
            float o1 = (oacc[dg][1] + q0.y) * inv0;
            float o2 = (oacc[dg][2] + q1.x) * inv1;
            float o3 = (oacc[dg][3] + q1.y) * inv1;
            size_t off0 = (size_t)row0 * CC + h * DH + dg * 8 + cq;
            size_t off1 = (size_t)(row0 + 8) * CC + h * DH + dg * 8 + cq;
            *(uint32_t*)&g_att_hi[off0] = pk_bf16x2(o0, o1);
            *(uint32_t*)&g_att_lo[off0] = pk_bf16x2(bf_res(o0), bf_res(o1));
            *(uint32_t*)&g_att_hi[off1] = pk_bf16x2(o2, o3);
            *(uint32_t*)&g_att_lo[off1] = pk_bf16x2(bf_res(o2), bf_res(o3));
        }
    }
}

// ---------------------------------------------------------------------------
// Kernel 5: scatter/transpose  proj[(bt*W+w), h, c] -> out(B,T,C,H,W)
// ---------------------------------------------------------------------------
__global__ void scatter_out_kernel(float* __restrict__ out) {
    __shared__ float tile[32][33];
    const int bt = blockIdx.z >> 7;
    const int h  = blockIdx.z & 127;
    const int wbase = blockIdx.x * 32;
    const int cbase = blockIdx.y * 32;
    const int tx = threadIdx.x, ty = threadIdx.y;

#pragma unroll
    for (int i = 0; i < 4; i++) {
        int w = wbase + ty + i * 8;
        tile[ty + i * 8][tx] = g_proj[((size_t)(bt * WW + w) * LL + h) * CC + cbase + tx];
    }
    __syncthreads();
    float* ob = out + (size_t)bt * CC * HH * WW + (size_t)h * WW;
#pragma unroll
    for (int i = 0; i < 4; i++) {
        int c = cbase + ty + i * 8;
        ob[(size_t)c * (HH * WW) + wbase + tx] = tile[tx][ty + i * 8];
    }
}

// ---------------------------------------------------------------------------
extern "C" void kernel_launch(void* const* d_in, const int* in_sizes, int n_in,
                              void* d_out, int out_size) {
    const float* x        = (const float*)d_in[0];
    const float* rel_bias = (const float*)d_in[1];
    const float* Wqkv     = (const float*)d_in[2];
    const float* bqkv     = (const float*)d_in[3];
    const float* Wout     = (const float*)d_in[4];
    const float* bout     = (const float*)d_in[5];
    float* out = (float*)d_out;

    void *p_qkv, *p_proj;
    void *p_shi, *p_slo, *p_ahi, *p_alo;
    void *p_wqh, *p_wql, *p_woh, *p_wol;
    cudaGetSymbolAddress(&p_qkv,  g_qkv);
    cudaGetSymbolAddress(&p_proj, g_proj);
    cudaGetSymbolAddress(&p_shi, g_seq_hi);
    cudaGetSymbolAddress(&p_slo, g_seq_lo);
    cudaGetSymbolAddress(&p_ahi, g_att_hi);
    cudaGetSymbolAddress(&p_alo, g_att_lo);
    cudaGetSymbolAddress(&p_wqh, g_WqkvT_hi);
    cudaGetSymbolAddress(&p_wql, g_WqkvT_lo);
    cudaGetSymbolAddress(&p_woh, g_WoutT_hi);
    cudaGetSymbolAddress(&p_wol, g_WoutT_lo);

    cudaFuncSetAttribute(gemm_mma_kernel,
                         cudaFuncAttributeMaxDynamicSharedMemorySize,
                         GEMM_SMEM);

    // 1) gather x -> seq hi/lo (bf16 split)
    gather_seq_kernel<<<dim3(WW / 32, CC / 32, BT * HH), dim3(32, 8)>>>(x);

    // 1b) weight transpose + split
    wprep_kernel<<<(3 * CC * CC + 255) / 256, 256>>>(Wqkv, Wout);

    // 2) qkv = seq @ Wqkv + bqkv   (mma.sync bf16x3, cp.async pipeline)
    gemm_mma_kernel<<<dim3(3 * CC / 128, MROWS / 128), 256, GEMM_SMEM>>>(
        (const __nv_bfloat16*)p_shi, (const __nv_bfloat16*)p_slo,
        (const __nv_bfloat16*)p_wqh, (const __nv_bfloat16*)p_wql,
        bqkv, (float*)p_qkv, 3 * CC);

    // 3) attention (tensor-core), CTA = (n, head, half)
    attention_mma_kernel<<<NSEQ * HEADS * 2, 256>>>(rel_bias);

    // 4) proj = att @ Wout + bout  (mma.sync bf16x3, cp.async pipeline)
    gemm_mma_kernel<<<dim3(CC / 128, MROWS / 128), 256, GEMM_SMEM>>>(
        (const __nv_bfloat16*)p_ahi, (const __nv_bfloat16*)p_alo,
        (const __nv_bfloat16*)p_woh, (const __nv_bfloat16*)p_wol,
        bout, (float*)p_proj, CC);

    // 5) scatter proj -> out
    scatter_out_kernel<<<dim3(WW / 32, CC / 32, BT * HH), dim3(32, 8)>>>(out);
}